// round 1
// baseline (speedup 1.0000x reference)
#include <cuda_runtime.h>
#include <cuda_bf16.h>
#include <math.h>

// Problem constants
#define BB 2
#define CC 128
#define GG 4
#define CG 32           // channels per group
#define NS 4096         // 16*16*16 tokens
#define SCALE 0.08838834764831845f  // 128^-0.5

// ---------------- scratch (device globals; no allocation allowed) ----------
__device__ float g_hn[BB * CC * NS];  // norm_1(x)
__device__ float g_cn[BB * CC * NS];  // norm_2(c)
__device__ float g_q [BB * CC * NS];
__device__ float g_k [BB * CC * NS];
__device__ float g_v [BB * CC * NS];
__device__ float g_o [BB * CC * NS];  // attention output pre-projection

// ---------------- GroupNorm --------------------------------------------------
// grid = BB*GG blocks, 512 threads. Two passes over the group (32ch x 4096).
__global__ void gn_kernel(const float* __restrict__ in,
                          const float* __restrict__ gamma,
                          const float* __restrict__ beta,
                          int which)   // 0 -> g_hn, 1 -> g_cn
{
    float* out = which ? g_cn : g_hn;
    int b = blockIdx.x >> 2;
    int g = blockIdx.x & 3;
    const size_t base = ((size_t)(b * CC + g * CG)) * NS;
    const float4* p4 = (const float4*)(in + base);
    const int M4 = CG * NS / 4;  // 32768 float4s

    float s = 0.f, ss = 0.f;
    for (int i = threadIdx.x; i < M4; i += blockDim.x) {
        float4 v = p4[i];
        s  += v.x + v.y + v.z + v.w;
        ss += v.x * v.x + v.y * v.y + v.z * v.z + v.w * v.w;
    }
    __shared__ float sh[64];
    #pragma unroll
    for (int o = 16; o; o >>= 1) {
        s  += __shfl_xor_sync(0xffffffffu, s, o);
        ss += __shfl_xor_sync(0xffffffffu, ss, o);
    }
    int w = threadIdx.x >> 5, ln = threadIdx.x & 31;
    if (ln == 0) { sh[w] = s; sh[32 + w] = ss; }
    __syncthreads();
    if (threadIdx.x < 32) {
        int nw = blockDim.x >> 5;
        s  = (threadIdx.x < nw) ? sh[threadIdx.x] : 0.f;
        ss = (threadIdx.x < nw) ? sh[32 + threadIdx.x] : 0.f;
        #pragma unroll
        for (int o = 16; o; o >>= 1) {
            s  += __shfl_xor_sync(0xffffffffu, s, o);
            ss += __shfl_xor_sync(0xffffffffu, ss, o);
        }
        if (threadIdx.x == 0) { sh[0] = s; sh[1] = ss; }
    }
    __syncthreads();
    const float invM = 1.0f / (float)(CG * NS);
    float mean = sh[0] * invM;
    float var  = sh[1] * invM - mean * mean;
    float rinv = rsqrtf(var + 1e-6f);

    float4* o4 = (float4*)(out + base);
    for (int i = threadIdx.x; i < M4; i += blockDim.x) {
        int ch = g * CG + (i >> 10);   // (i*4)/4096
        float ga = gamma[ch] * rinv;
        float be = beta[ch] - mean * ga;
        float4 v = p4[i];
        v.x = v.x * ga + be; v.y = v.y * ga + be;
        v.z = v.z * ga + be; v.w = v.w * ga + be;
        o4[i] = v;
    }
}

// ---------------- 1x1x1 conv (channel-mixing GEMM) --------------------------
// out[b,o,n] = sum_c W[o,c] * in[b,c,n] + bias[o]
// grid (N/64, B, 3): z=0 Q from g_cn, z=1 K from g_hn, z=2 V from g_hn.
// 256 threads, dynamic smem: Wt[128][128] (transposed) + Ins[128][64].
__global__ void __launch_bounds__(256) qkv_kernel(
    const float* __restrict__ wq, const float* __restrict__ bq,
    const float* __restrict__ wk, const float* __restrict__ bk,
    const float* __restrict__ wv, const float* __restrict__ bv)
{
    extern __shared__ float sm[];
    float* Wt  = sm;              // [c][o] : 128*128
    float* Ins = sm + CC * CC;    // [c][64]

    int z = blockIdx.z;
    const float* in   = (z == 0) ? g_cn : g_hn;
    const float* w    = (z == 0) ? wq : (z == 1 ? wk : wv);
    const float* bias = (z == 0) ? bq : (z == 1 ? bk : bv);
    float* out        = (z == 0) ? g_q : (z == 1 ? g_k : g_v);

    int b  = blockIdx.y;
    int n0 = blockIdx.x * 64;

    for (int idx = threadIdx.x; idx < CC * CC; idx += 256) {
        int o = idx >> 7, c = idx & 127;        // coalesced read of w[o][c]
        Wt[c * CC + o] = w[idx];
    }
    for (int idx = threadIdx.x; idx < CC * 16; idx += 256) {
        int c = idx >> 4, col = idx & 15;
        *(float4*)&Ins[c * 64 + col * 4] =
            *(const float4*)&in[((size_t)b * CC + c) * NS + n0 + col * 4];
    }
    __syncthreads();

    int nl = threadIdx.x & 63;
    int ob = (threadIdx.x >> 6) * 32;
    float acc[32];
    #pragma unroll
    for (int i = 0; i < 32; i++) acc[i] = 0.f;

    #pragma unroll 4
    for (int c = 0; c < CC; c++) {
        float iv = Ins[c * 64 + nl];
        const float* wr = &Wt[c * CC + ob];
        #pragma unroll
        for (int oo = 0; oo < 32; oo += 4) {
            float4 w4 = *(const float4*)&wr[oo];
            acc[oo + 0] += w4.x * iv;
            acc[oo + 1] += w4.y * iv;
            acc[oo + 2] += w4.z * iv;
            acc[oo + 3] += w4.w * iv;
        }
    }
    #pragma unroll
    for (int oo = 0; oo < 32; oo++) {
        int o = ob + oo;
        out[((size_t)b * CC + o) * NS + n0 + nl] = acc[oo] + bias[o];
    }
}

// Final projection + residual: out = x + W*g_o + bias. grid (N/64, B).
__global__ void __launch_bounds__(256) proj_out_kernel(
    const float* __restrict__ w, const float* __restrict__ bias,
    const float* __restrict__ xres, float* __restrict__ out)
{
    extern __shared__ float sm[];
    float* Wt  = sm;
    float* Ins = sm + CC * CC;

    int b  = blockIdx.y;
    int n0 = blockIdx.x * 64;

    for (int idx = threadIdx.x; idx < CC * CC; idx += 256) {
        int o = idx >> 7, c = idx & 127;
        Wt[c * CC + o] = w[idx];
    }
    for (int idx = threadIdx.x; idx < CC * 16; idx += 256) {
        int c = idx >> 4, col = idx & 15;
        *(float4*)&Ins[c * 64 + col * 4] =
            *(const float4*)&g_o[((size_t)b * CC + c) * NS + n0 + col * 4];
    }
    __syncthreads();

    int nl = threadIdx.x & 63;
    int ob = (threadIdx.x >> 6) * 32;
    float acc[32];
    #pragma unroll
    for (int i = 0; i < 32; i++) acc[i] = 0.f;

    #pragma unroll 4
    for (int c = 0; c < CC; c++) {
        float iv = Ins[c * 64 + nl];
        const float* wr = &Wt[c * CC + ob];
        #pragma unroll
        for (int oo = 0; oo < 32; oo += 4) {
            float4 w4 = *(const float4*)&wr[oo];
            acc[oo + 0] += w4.x * iv;
            acc[oo + 1] += w4.y * iv;
            acc[oo + 2] += w4.z * iv;
            acc[oo + 3] += w4.w * iv;
        }
    }
    #pragma unroll
    for (int oo = 0; oo < 32; oo++) {
        int o = ob + oo;
        size_t gi = ((size_t)b * CC + o) * NS + n0 + nl;
        out[gi] = acc[oo] + bias[o] + xres[gi];
    }
}

// ---------------- flash attention (fp32) ------------------------------------
// grid (NS/64, BB), 256 threads. BM=BN=64, d=128.
// Thread (ti=tid/16, tj=tid%16): S 4x4 tile (i=4ti.., j=4tj..),
// O 4x8 tile (i=4ti.., c=8tj..). Online softmax, exact.
__global__ void __launch_bounds__(256, 1) attn_kernel()
{
    extern __shared__ float sm[];
    float* Qs = sm;                   // [128][64]
    float* Ks = Qs + 128 * 64;        // [128][64]
    float* Vs = Ks + 128 * 64;        // [64][132] (transposed, padded)
    float* Ps = Vs + 64 * 132;        // [64][68]

    int b  = blockIdx.y;
    int i0 = blockIdx.x * 64;
    int tid = threadIdx.x;
    int ti = tid >> 4, tj = tid & 15;

    // load Q tile (scaled)
    for (int idx = tid; idx < 2048; idx += 256) {
        int c = idx >> 4, col = idx & 15;
        float4 v = *(const float4*)&g_q[((size_t)b * CC + c) * NS + i0 + col * 4];
        v.x *= SCALE; v.y *= SCALE; v.z *= SCALE; v.w *= SCALE;
        *(float4*)&Qs[c * 64 + col * 4] = v;
    }

    float m[4], l[4], O[4][8];
    #pragma unroll
    for (int ii = 0; ii < 4; ii++) {
        m[ii] = -1e30f; l[ii] = 0.f;
        #pragma unroll
        for (int cc = 0; cc < 8; cc++) O[ii][cc] = 0.f;
    }

    for (int j0 = 0; j0 < NS; j0 += 64) {
        __syncthreads();   // previous iteration done with Ks/Vs/Ps
        for (int idx = tid; idx < 2048; idx += 256) {
            int c = idx >> 4, col = idx & 15;
            *(float4*)&Ks[c * 64 + col * 4] =
                *(const float4*)&g_k[((size_t)b * CC + c) * NS + j0 + col * 4];
        }
        for (int idx = tid; idx < 8192; idx += 256) {
            int c = idx >> 6, j = idx & 63;
            Vs[j * 132 + c] = g_v[((size_t)b * CC + c) * NS + j0 + j];
        }
        __syncthreads();

        // S = Q^T K  (4x4 per thread)
        float S[4][4];
        #pragma unroll
        for (int a = 0; a < 4; a++)
            #pragma unroll
            for (int e = 0; e < 4; e++) S[a][e] = 0.f;

        #pragma unroll 4
        for (int c = 0; c < 128; c++) {
            float4 q = *(const float4*)&Qs[c * 64 + ti * 4];
            float4 k = *(const float4*)&Ks[c * 64 + tj * 4];
            S[0][0] += q.x * k.x; S[0][1] += q.x * k.y; S[0][2] += q.x * k.z; S[0][3] += q.x * k.w;
            S[1][0] += q.y * k.x; S[1][1] += q.y * k.y; S[1][2] += q.y * k.z; S[1][3] += q.y * k.w;
            S[2][0] += q.z * k.x; S[2][1] += q.z * k.y; S[2][2] += q.z * k.z; S[2][3] += q.z * k.w;
            S[3][0] += q.w * k.x; S[3][1] += q.w * k.y; S[3][2] += q.w * k.z; S[3][3] += q.w * k.w;
        }

        // online softmax per row (reduce across the 16 tj-lanes of this ti)
        #pragma unroll
        for (int ii = 0; ii < 4; ii++) {
            float mx = fmaxf(fmaxf(S[ii][0], S[ii][1]), fmaxf(S[ii][2], S[ii][3]));
            #pragma unroll
            for (int o = 8; o; o >>= 1)
                mx = fmaxf(mx, __shfl_xor_sync(0xffffffffu, mx, o));
            float mn = fmaxf(m[ii], mx);
            float corr = __expf(m[ii] - mn);
            float rs = 0.f;
            #pragma unroll
            for (int jj = 0; jj < 4; jj++) {
                float p = __expf(S[ii][jj] - mn);
                S[ii][jj] = p; rs += p;
            }
            #pragma unroll
            for (int o = 8; o; o >>= 1)
                rs += __shfl_xor_sync(0xffffffffu, rs, o);
            l[ii] = l[ii] * corr + rs;
            m[ii] = mn;
            #pragma unroll
            for (int cc = 0; cc < 8; cc++) O[ii][cc] *= corr;
            *(float4*)&Ps[(ti * 4 + ii) * 68 + tj * 4] =
                make_float4(S[ii][0], S[ii][1], S[ii][2], S[ii][3]);
        }
        __syncthreads();

        // O += P * V^T  (P from smem, V transposed in smem)
        #pragma unroll 2
        for (int j = 0; j < 64; j++) {
            float4 v0 = *(const float4*)&Vs[j * 132 + tj * 8];
            float4 v1 = *(const float4*)&Vs[j * 132 + tj * 8 + 4];
            #pragma unroll
            for (int ii = 0; ii < 4; ii++) {
                float p = Ps[(ti * 4 + ii) * 68 + j];
                O[ii][0] += p * v0.x; O[ii][1] += p * v0.y;
                O[ii][2] += p * v0.z; O[ii][3] += p * v0.w;
                O[ii][4] += p * v1.x; O[ii][5] += p * v1.y;
                O[ii][6] += p * v1.z; O[ii][7] += p * v1.w;
            }
        }
    }

    // epilogue: normalize and write g_o[b][c][i]
    #pragma unroll
    for (int ii = 0; ii < 4; ii++) {
        float inv = 1.0f / l[ii];
        #pragma unroll
        for (int cc = 0; cc < 8; cc++) {
            g_o[((size_t)b * CC + (tj * 8 + cc)) * NS + i0 + ti * 4 + ii] = O[ii][cc] * inv;
        }
    }
}

// ---------------- launcher ---------------------------------------------------
extern "C" void kernel_launch(void* const* d_in, const int* in_sizes, int n_in,
                              void* d_out, int out_size)
{
    const float* x  = (const float*)d_in[0];
    const float* c  = (const float*)d_in[1];
    const float* g1 = (const float*)d_in[2];
    const float* b1 = (const float*)d_in[3];
    const float* g2 = (const float*)d_in[4];
    const float* b2 = (const float*)d_in[5];
    const float* wq = (const float*)d_in[6];
    const float* bq = (const float*)d_in[7];
    const float* wk = (const float*)d_in[8];
    const float* bk = (const float*)d_in[9];
    const float* wv = (const float*)d_in[10];
    const float* bv = (const float*)d_in[11];
    const float* wp = (const float*)d_in[12];
    const float* bp = (const float*)d_in[13];
    float* out = (float*)d_out;

    const int PROJ_SMEM = (CC * CC + CC * 64) * 4;                     // 98304 B
    const int ATTN_SMEM = (128 * 64 + 128 * 64 + 64 * 132 + 64 * 68) * 4; // 116736 B
    cudaFuncSetAttribute(qkv_kernel,      cudaFuncAttributeMaxDynamicSharedMemorySize, PROJ_SMEM);
    cudaFuncSetAttribute(proj_out_kernel, cudaFuncAttributeMaxDynamicSharedMemorySize, PROJ_SMEM);
    cudaFuncSetAttribute(attn_kernel,     cudaFuncAttributeMaxDynamicSharedMemorySize, ATTN_SMEM);

    gn_kernel<<<BB * GG, 512>>>(x, g1, b1, 0);   // h_ = GN(x)
    gn_kernel<<<BB * GG, 512>>>(c, g2, b2, 1);   // c_ = GN(c)

    dim3 gq(NS / 64, BB, 3);
    qkv_kernel<<<gq, 256, PROJ_SMEM>>>(wq, bq, wk, bk, wv, bv);

    dim3 ga(NS / 64, BB);
    attn_kernel<<<ga, 256, ATTN_SMEM>>>();

    dim3 gp(NS / 64, BB);
    proj_out_kernel<<<gp, 256, PROJ_SMEM>>>(wp, bp, x, out);
}

// round 2
// speedup vs baseline: 4.1807x; 4.1807x over previous
#include <cuda_runtime.h>
#include <cuda_bf16.h>
#include <math.h>
#include <stdint.h>

// Problem constants
#define BB 2
#define CC 128
#define GG 4
#define CG 32
#define NS 4096
// 128^-0.5 * log2(e): fold into Q so softmax works in exp2 domain
#define QSCALE 0.12751744154339495f

// ---------------- scratch (device globals) ----------------------------------
__device__ float g_hn[BB * CC * NS];          // norm_1(x)
__device__ float g_cn[BB * CC * NS];          // norm_2(c)
__device__ float g_o [BB * CC * NS];          // attention output (fp32)
__device__ __nv_bfloat16 g_qh[BB * CC * NS];  // Q * QSCALE, bf16, [b][c][n]
__device__ __nv_bfloat16 g_kh[BB * CC * NS];  // K bf16
__device__ __nv_bfloat16 g_vh[BB * CC * NS];  // V bf16

// ---------------- small asm helpers ------------------------------------------
__device__ __forceinline__ float ex2(float x) {
    float r; asm("ex2.approx.ftz.f32 %0, %1;" : "=f"(r) : "f"(x)); return r;
}
__device__ __forceinline__ uint32_t pack_bf16(float lo, float hi) {
    uint32_t d;
    asm("cvt.rn.bf16x2.f32 %0, %1, %2;" : "=r"(d) : "f"(hi), "f"(lo));
    return d;
}
__device__ __forceinline__ void cp16(void* dst_smem, const void* src) {
    uint32_t d = (uint32_t)__cvta_generic_to_shared(dst_smem);
    asm volatile("cp.async.cg.shared.global [%0], [%1], 16;\n" :: "r"(d), "l"(src));
}
__device__ __forceinline__ void ldsm_x4(uint32_t* r, const void* p) {
    uint32_t a = (uint32_t)__cvta_generic_to_shared(p);
    asm volatile("ldmatrix.sync.aligned.m8n8.x4.shared.b16 {%0,%1,%2,%3}, [%4];"
        : "=r"(r[0]), "=r"(r[1]), "=r"(r[2]), "=r"(r[3]) : "r"(a));
}
__device__ __forceinline__ void ldsm_x4t(uint32_t* r, const void* p) {
    uint32_t a = (uint32_t)__cvta_generic_to_shared(p);
    asm volatile("ldmatrix.sync.aligned.m8n8.x4.trans.shared.b16 {%0,%1,%2,%3}, [%4];"
        : "=r"(r[0]), "=r"(r[1]), "=r"(r[2]), "=r"(r[3]) : "r"(a));
}
__device__ __forceinline__ void mma16816(float* d, const uint32_t* a, const uint32_t* b) {
    asm volatile(
        "mma.sync.aligned.m16n8k16.row.col.f32.bf16.bf16.f32 "
        "{%0,%1,%2,%3},{%4,%5,%6,%7},{%8,%9},{%0,%1,%2,%3};"
        : "+f"(d[0]), "+f"(d[1]), "+f"(d[2]), "+f"(d[3])
        : "r"(a[0]), "r"(a[1]), "r"(a[2]), "r"(a[3]), "r"(b[0]), "r"(b[1]));
}

// ---------------- GroupNorm ---------------------------------------------------
__global__ void gn_kernel(const float* __restrict__ in,
                          const float* __restrict__ gamma,
                          const float* __restrict__ beta,
                          int which)
{
    float* out = which ? g_cn : g_hn;
    int b = blockIdx.x >> 2;
    int g = blockIdx.x & 3;
    const size_t base = ((size_t)(b * CC + g * CG)) * NS;
    const float4* p4 = (const float4*)(in + base);
    const int M4 = CG * NS / 4;

    float s = 0.f, ss = 0.f;
    for (int i = threadIdx.x; i < M4; i += blockDim.x) {
        float4 v = p4[i];
        s  += v.x + v.y + v.z + v.w;
        ss += v.x * v.x + v.y * v.y + v.z * v.z + v.w * v.w;
    }
    __shared__ float sh[64];
    #pragma unroll
    for (int o = 16; o; o >>= 1) {
        s  += __shfl_xor_sync(0xffffffffu, s, o);
        ss += __shfl_xor_sync(0xffffffffu, ss, o);
    }
    int w = threadIdx.x >> 5, ln = threadIdx.x & 31;
    if (ln == 0) { sh[w] = s; sh[32 + w] = ss; }
    __syncthreads();
    if (threadIdx.x < 32) {
        int nw = blockDim.x >> 5;
        s  = (threadIdx.x < nw) ? sh[threadIdx.x] : 0.f;
        ss = (threadIdx.x < nw) ? sh[32 + threadIdx.x] : 0.f;
        #pragma unroll
        for (int o = 16; o; o >>= 1) {
            s  += __shfl_xor_sync(0xffffffffu, s, o);
            ss += __shfl_xor_sync(0xffffffffu, ss, o);
        }
        if (threadIdx.x == 0) { sh[0] = s; sh[1] = ss; }
    }
    __syncthreads();
    const float invM = 1.0f / (float)(CG * NS);
    float mean = sh[0] * invM;
    float var  = sh[1] * invM - mean * mean;
    float rinv = rsqrtf(var + 1e-6f);

    float4* o4 = (float4*)(out + base);
    for (int i = threadIdx.x; i < M4; i += blockDim.x) {
        int ch = g * CG + (i >> 10);
        float ga = gamma[ch] * rinv;
        float be = beta[ch] - mean * ga;
        float4 v = p4[i];
        v.x = v.x * ga + be; v.y = v.y * ga + be;
        v.z = v.z * ga + be; v.w = v.w * ga + be;
        o4[i] = v;
    }
}

// ---------------- QKV projection (fp32 FFMA, bf16 output) --------------------
__global__ void __launch_bounds__(256) qkv_kernel(
    const float* __restrict__ wq, const float* __restrict__ bq,
    const float* __restrict__ wk, const float* __restrict__ bk,
    const float* __restrict__ wv, const float* __restrict__ bv)
{
    extern __shared__ float sm[];
    float* Wt  = sm;
    float* Ins = sm + CC * CC;

    int z = blockIdx.z;
    const float* in   = (z == 0) ? g_cn : g_hn;
    const float* w    = (z == 0) ? wq : (z == 1 ? wk : wv);
    const float* bias = (z == 0) ? bq : (z == 1 ? bk : bv);
    __nv_bfloat16* out = (z == 0) ? g_qh : (z == 1 ? g_kh : g_vh);

    int b  = blockIdx.y;
    int n0 = blockIdx.x * 64;

    for (int idx = threadIdx.x; idx < CC * CC; idx += 256) {
        int o = idx >> 7, c = idx & 127;
        Wt[c * CC + o] = w[idx];
    }
    for (int idx = threadIdx.x; idx < CC * 16; idx += 256) {
        int c = idx >> 4, col = idx & 15;
        *(float4*)&Ins[c * 64 + col * 4] =
            *(const float4*)&in[((size_t)b * CC + c) * NS + n0 + col * 4];
    }
    __syncthreads();

    int nl = threadIdx.x & 63;
    int ob = (threadIdx.x >> 6) * 32;
    float acc[32];
    #pragma unroll
    for (int i = 0; i < 32; i++) acc[i] = 0.f;

    #pragma unroll 4
    for (int c = 0; c < CC; c++) {
        float iv = Ins[c * 64 + nl];
        const float* wr = &Wt[c * CC + ob];
        #pragma unroll
        for (int oo = 0; oo < 32; oo += 4) {
            float4 w4 = *(const float4*)&wr[oo];
            acc[oo + 0] += w4.x * iv;
            acc[oo + 1] += w4.y * iv;
            acc[oo + 2] += w4.z * iv;
            acc[oo + 3] += w4.w * iv;
        }
    }
    float sc = (z == 0) ? QSCALE : 1.0f;
    #pragma unroll
    for (int oo = 0; oo < 32; oo++) {
        int o = ob + oo;
        out[((size_t)b * CC + o) * NS + n0 + nl] =
            __float2bfloat16((acc[oo] + bias[o]) * sc);
    }
}

// ---------------- output projection + residual (fp32) ------------------------
__global__ void __launch_bounds__(256) proj_out_kernel(
    const float* __restrict__ w, const float* __restrict__ bias,
    const float* __restrict__ xres, float* __restrict__ out)
{
    extern __shared__ float sm[];
    float* Wt  = sm;
    float* Ins = sm + CC * CC;

    int b  = blockIdx.y;
    int n0 = blockIdx.x * 64;

    for (int idx = threadIdx.x; idx < CC * CC; idx += 256) {
        int o = idx >> 7, c = idx & 127;
        Wt[c * CC + o] = w[idx];
    }
    for (int idx = threadIdx.x; idx < CC * 16; idx += 256) {
        int c = idx >> 4, col = idx & 15;
        *(float4*)&Ins[c * 64 + col * 4] =
            *(const float4*)&g_o[((size_t)b * CC + c) * NS + n0 + col * 4];
    }
    __syncthreads();

    int nl = threadIdx.x & 63;
    int ob = (threadIdx.x >> 6) * 32;
    float acc[32];
    #pragma unroll
    for (int i = 0; i < 32; i++) acc[i] = 0.f;

    #pragma unroll 4
    for (int c = 0; c < CC; c++) {
        float iv = Ins[c * 64 + nl];
        const float* wr = &Wt[c * CC + ob];
        #pragma unroll
        for (int oo = 0; oo < 32; oo += 4) {
            float4 w4 = *(const float4*)&wr[oo];
            acc[oo + 0] += w4.x * iv;
            acc[oo + 1] += w4.y * iv;
            acc[oo + 2] += w4.z * iv;
            acc[oo + 3] += w4.w * iv;
        }
    }
    #pragma unroll
    for (int oo = 0; oo < 32; oo++) {
        int o = ob + oo;
        size_t gi = ((size_t)b * CC + o) * NS + n0 + nl;
        out[gi] = acc[oo] + bias[o] + xres[gi];
    }
}

// ---------------- flash attention, bf16 mma.sync ------------------------------
// grid (NS/64, BB), 128 threads (4 warps). BM=64 (16 rows/warp), BN=64, d=128.
// All tiles kept in natural [c][n] smem layout (ld = 72 bf16 -> 144B row stride,
// 16B-phase-shifted => conflict-free ldmatrix).
#define LDB 72
#define SM_TILE (128 * LDB)   // bf16 elements per tile buffer

__global__ void __launch_bounds__(128) attn_kernel()
{
    extern __shared__ __nv_bfloat16 sh[];
    __nv_bfloat16* Qs = sh;                        // [128][LDB]
    // double-buffered K/V
    __nv_bfloat16* Ksb[2] = { sh + SM_TILE,     sh + 2 * SM_TILE };
    __nv_bfloat16* Vsb[2] = { sh + 3 * SM_TILE, sh + 4 * SM_TILE };

    int b  = blockIdx.y;
    int i0 = blockIdx.x * 64;
    int tid = threadIdx.x, lane = tid & 31, warp = tid >> 5;
    int t = lane & 3;
    int m0 = warp * 16;

    const __nv_bfloat16* gq = g_qh + (size_t)b * CC * NS + i0;
    const __nv_bfloat16* gk = g_kh + (size_t)b * CC * NS;
    const __nv_bfloat16* gv = g_vh + (size_t)b * CC * NS;

    // async copy Q tile + KV tile 0
    for (int idx = tid; idx < 1024; idx += 128) {
        int c = idx >> 3, j8 = (idx & 7) * 8;
        cp16(&Qs[c * LDB + j8], gq + (size_t)c * NS + j8);
        cp16(&Ksb[0][c * LDB + j8], gk + (size_t)c * NS + j8);
        cp16(&Vsb[0][c * LDB + j8], gv + (size_t)c * NS + j8);
    }
    asm volatile("cp.async.commit_group;");
    asm volatile("cp.async.wait_group 0;");
    __syncthreads();

    // per-lane ldmatrix address offsets (same shape for Q/V, K differs)
    const int rowA = (lane & 7) + ((lane & 16) ? 8 : 0);  // Q & V: row = c-offset
    const int colA = ((lane & 8) ? 8 : 0);                // Q & V: col offset
    const int rowK = (lane & 7) + ((lane & 8) ? 8 : 0);   // K: row = c-offset
    const int colK = ((lane & 16) ? 8 : 0);               // K: col offset (j)

    // Q a-frags (8 k-blocks of 16 channels), via x4.trans on [c][i] layout
    uint32_t qa[8][4];
    #pragma unroll
    for (int kb = 0; kb < 8; kb++)
        ldsm_x4t(qa[kb], &Qs[(kb * 16 + rowA) * LDB + m0 + colA]);

    float mr0 = -1e30f, mr1 = -1e30f, lr0 = 0.f, lr1 = 0.f;
    float of[16][4];
    #pragma unroll
    for (int nt = 0; nt < 16; nt++)
        #pragma unroll
        for (int e = 0; e < 4; e++) of[nt][e] = 0.f;

    const int NT = NS / 64;
    for (int jt = 0; jt < NT; jt++) {
        const int cur = jt & 1;
        // prefetch next tile into other buffer
        if (jt + 1 < NT) {
            int j0n = (jt + 1) * 64, nb = (jt + 1) & 1;
            for (int idx = tid; idx < 1024; idx += 128) {
                int c = idx >> 3, j8 = (idx & 7) * 8;
                cp16(&Ksb[nb][c * LDB + j8], gk + (size_t)c * NS + j0n + j8);
                cp16(&Vsb[nb][c * LDB + j8], gv + (size_t)c * NS + j0n + j8);
            }
        }
        asm volatile("cp.async.commit_group;");
        asm volatile("cp.async.wait_group 1;");
        __syncthreads();

        const __nv_bfloat16* Ks = Ksb[cur];
        const __nv_bfloat16* Vs = Vsb[cur];

        // ---- S = Q^T K (log2-domain scores; QSCALE folded into Q) ----
        float sf[8][4];
        #pragma unroll
        for (int nb = 0; nb < 8; nb++)
            #pragma unroll
            for (int e = 0; e < 4; e++) sf[nb][e] = 0.f;

        #pragma unroll
        for (int kb = 0; kb < 8; kb++) {
            #pragma unroll
            for (int nbp = 0; nbp < 4; nbp++) {
                uint32_t kf[4];
                ldsm_x4t(kf, &Ks[(kb * 16 + rowK) * LDB + nbp * 16 + colK]);
                mma16816(sf[2 * nbp],     qa[kb], kf);
                mma16816(sf[2 * nbp + 1], qa[kb], kf + 2);
            }
        }

        // ---- online softmax (rows g and g+8; reduce over 4 t-lanes) ----
        float mx0 = -1e30f, mx1 = -1e30f;
        #pragma unroll
        for (int nb = 0; nb < 8; nb++) {
            mx0 = fmaxf(mx0, fmaxf(sf[nb][0], sf[nb][1]));
            mx1 = fmaxf(mx1, fmaxf(sf[nb][2], sf[nb][3]));
        }
        mx0 = fmaxf(mx0, __shfl_xor_sync(0xffffffffu, mx0, 1));
        mx0 = fmaxf(mx0, __shfl_xor_sync(0xffffffffu, mx0, 2));
        mx1 = fmaxf(mx1, __shfl_xor_sync(0xffffffffu, mx1, 1));
        mx1 = fmaxf(mx1, __shfl_xor_sync(0xffffffffu, mx1, 2));

        float mn0 = fmaxf(mr0, mx0), mn1 = fmaxf(mr1, mx1);
        float cr0 = ex2(mr0 - mn0),  cr1 = ex2(mr1 - mn1);
        float rs0 = 0.f, rs1 = 0.f;
        #pragma unroll
        for (int nb = 0; nb < 8; nb++) {
            sf[nb][0] = ex2(sf[nb][0] - mn0);
            sf[nb][1] = ex2(sf[nb][1] - mn0);
            sf[nb][2] = ex2(sf[nb][2] - mn1);
            sf[nb][3] = ex2(sf[nb][3] - mn1);
            rs0 += sf[nb][0] + sf[nb][1];
            rs1 += sf[nb][2] + sf[nb][3];
        }
        rs0 += __shfl_xor_sync(0xffffffffu, rs0, 1);
        rs0 += __shfl_xor_sync(0xffffffffu, rs0, 2);
        rs1 += __shfl_xor_sync(0xffffffffu, rs1, 1);
        rs1 += __shfl_xor_sync(0xffffffffu, rs1, 2);
        lr0 = lr0 * cr0 + rs0;
        lr1 = lr1 * cr1 + rs1;
        mr0 = mn0; mr1 = mn1;

        #pragma unroll
        for (int nt = 0; nt < 16; nt++) {
            of[nt][0] *= cr0; of[nt][1] *= cr0;
            of[nt][2] *= cr1; of[nt][3] *= cr1;
        }

        // ---- P -> bf16 a-frags (register repack, no smem) ----
        uint32_t pa[4][4];
        #pragma unroll
        for (int kt = 0; kt < 4; kt++) {
            pa[kt][0] = pack_bf16(sf[2 * kt][0],     sf[2 * kt][1]);
            pa[kt][1] = pack_bf16(sf[2 * kt][2],     sf[2 * kt][3]);
            pa[kt][2] = pack_bf16(sf[2 * kt + 1][0], sf[2 * kt + 1][1]);
            pa[kt][3] = pack_bf16(sf[2 * kt + 1][2], sf[2 * kt + 1][3]);
        }

        // ---- O += P V^T : V in [c][j], non-trans ldmatrix gives b-frags ----
        #pragma unroll
        for (int ntp = 0; ntp < 8; ntp++) {
            #pragma unroll
            for (int kt = 0; kt < 4; kt++) {
                uint32_t vf[4];
                ldsm_x4(vf, &Vs[(ntp * 16 + rowA) * LDB + kt * 16 + colA]);
                mma16816(of[2 * ntp],     pa[kt], vf);
                mma16816(of[2 * ntp + 1], pa[kt], vf + 2);
            }
        }
        __syncthreads();   // everyone done reading cur before it gets overwritten
    }

    // ---- epilogue: normalize, write g_o[b][c][i] (fp32) ----
    float inv0 = 1.0f / lr0, inv1 = 1.0f / lr1;
    int ig = i0 + m0 + (lane >> 2);
    float* go = g_o + (size_t)b * CC * NS;
    #pragma unroll
    for (int nt = 0; nt < 16; nt++) {
        int c = 8 * nt + 2 * t;
        go[(size_t)c * NS + ig]           = of[nt][0] * inv0;
        go[(size_t)(c + 1) * NS + ig]     = of[nt][1] * inv0;
        go[(size_t)c * NS + ig + 8]       = of[nt][2] * inv1;
        go[(size_t)(c + 1) * NS + ig + 8] = of[nt][3] * inv1;
    }
}

// ---------------- launcher ---------------------------------------------------
extern "C" void kernel_launch(void* const* d_in, const int* in_sizes, int n_in,
                              void* d_out, int out_size)
{
    const float* x  = (const float*)d_in[0];
    const float* c  = (const float*)d_in[1];
    const float* g1 = (const float*)d_in[2];
    const float* b1 = (const float*)d_in[3];
    const float* g2 = (const float*)d_in[4];
    const float* b2 = (const float*)d_in[5];
    const float* wq = (const float*)d_in[6];
    const float* bq = (const float*)d_in[7];
    const float* wk = (const float*)d_in[8];
    const float* bk = (const float*)d_in[9];
    const float* wv = (const float*)d_in[10];
    const float* bv = (const float*)d_in[11];
    const float* wp = (const float*)d_in[12];
    const float* bp = (const float*)d_in[13];
    float* out = (float*)d_out;

    const int PROJ_SMEM = (CC * CC + CC * 64) * 4;      // 98304 B
    const int ATTN_SMEM = 5 * SM_TILE * 2;              // 92160 B
    cudaFuncSetAttribute(qkv_kernel,      cudaFuncAttributeMaxDynamicSharedMemorySize, PROJ_SMEM);
    cudaFuncSetAttribute(proj_out_kernel, cudaFuncAttributeMaxDynamicSharedMemorySize, PROJ_SMEM);
    cudaFuncSetAttribute(attn_kernel,     cudaFuncAttributeMaxDynamicSharedMemorySize, ATTN_SMEM);

    gn_kernel<<<BB * GG, 512>>>(x, g1, b1, 0);
    gn_kernel<<<BB * GG, 512>>>(c, g2, b2, 1);

    dim3 gq(NS / 64, BB, 3);
    qkv_kernel<<<gq, 256, PROJ_SMEM>>>(wq, bq, wk, bk, wv, bv);

    dim3 ga(NS / 64, BB);
    attn_kernel<<<ga, 128, ATTN_SMEM>>>();

    dim3 gp(NS / 64, BB);
    proj_out_kernel<<<gp, 256, PROJ_SMEM>>>(wp, bp, x, out);
}

// round 3
// speedup vs baseline: 7.2134x; 1.7254x over previous
#include <cuda_runtime.h>
#include <cuda_bf16.h>
#include <math.h>
#include <stdint.h>

// Problem constants
#define BB 2
#define CC 128
#define GG 4
#define CG 32
#define NS 4096
#define SPLIT 2
#define JSPAN (NS / SPLIT)          // 2048 keys per split
// 128^-0.5 * log2(e): fold into Q so softmax works in exp2 domain
#define QSCALE 0.12751744154339495f

// ---------------- scratch (device globals) ----------------------------------
__device__ __nv_bfloat16 g_qh[BB * CC * NS];   // Q * QSCALE, bf16, [b][c][n]
__device__ __nv_bfloat16 g_kh[BB * CC * NS];
__device__ __nv_bfloat16 g_vh[BB * CC * NS];
__device__ float g_po[SPLIT * BB * CC * NS];   // unnormalized partial O
__device__ float g_pm[SPLIT * BB * NS];        // partial row max (log2 domain)
__device__ float g_pl[SPLIT * BB * NS];        // partial row sum
__device__ float g_part[16][8][2];             // GN partial sums [group][slab][sum,ssq]

// ---------------- asm helpers -------------------------------------------------
__device__ __forceinline__ float ex2(float x) {
    float r; asm("ex2.approx.ftz.f32 %0, %1;" : "=f"(r) : "f"(x)); return r;
}
__device__ __forceinline__ uint32_t pack_bf16(float lo, float hi) {
    uint32_t d;
    asm("cvt.rn.bf16x2.f32 %0, %1, %2;" : "=r"(d) : "f"(hi), "f"(lo));
    return d;
}
__device__ __forceinline__ void cp16(void* dst_smem, const void* src) {
    uint32_t d = (uint32_t)__cvta_generic_to_shared(dst_smem);
    asm volatile("cp.async.cg.shared.global [%0], [%1], 16;\n" :: "r"(d), "l"(src));
}
__device__ __forceinline__ void ldsm_x4(uint32_t* r, const void* p) {
    uint32_t a = (uint32_t)__cvta_generic_to_shared(p);
    asm volatile("ldmatrix.sync.aligned.m8n8.x4.shared.b16 {%0,%1,%2,%3}, [%4];"
        : "=r"(r[0]), "=r"(r[1]), "=r"(r[2]), "=r"(r[3]) : "r"(a));
}
__device__ __forceinline__ void ldsm_x4t(uint32_t* r, const void* p) {
    uint32_t a = (uint32_t)__cvta_generic_to_shared(p);
    asm volatile("ldmatrix.sync.aligned.m8n8.x4.trans.shared.b16 {%0,%1,%2,%3}, [%4];"
        : "=r"(r[0]), "=r"(r[1]), "=r"(r[2]), "=r"(r[3]) : "r"(a));
}
__device__ __forceinline__ void mma16816(float* d, const uint32_t* a, const uint32_t* b) {
    asm volatile(
        "mma.sync.aligned.m16n8k16.row.col.f32.bf16.bf16.f32 "
        "{%0,%1,%2,%3},{%4,%5,%6,%7},{%8,%9},{%0,%1,%2,%3};"
        : "+f"(d[0]), "+f"(d[1]), "+f"(d[2]), "+f"(d[3])
        : "r"(a[0]), "r"(a[1]), "r"(a[2]), "r"(a[3]), "r"(b[0]), "r"(b[1]));
}

// ---------------- GroupNorm partial stats -------------------------------------
// grid (8 slabs, 16 groups), 256 threads. group gi = which*8 + b*4 + g.
__global__ void __launch_bounds__(256) gn_stats_kernel(
    const float* __restrict__ x, const float* __restrict__ c)
{
    int slab = blockIdx.x;
    int gi   = blockIdx.y;
    int which = gi >> 3, b = (gi >> 2) & 1, g = gi & 3;
    const float* in = which ? c : x;
    const float4* p4 = (const float4*)(in + ((size_t)(b * CC + g * CG)) * NS) +
                       (size_t)slab * 4096;   // 16384 floats per slab

    float s = 0.f, ss = 0.f;
    #pragma unroll 4
    for (int i = threadIdx.x; i < 4096; i += 256) {
        float4 v = p4[i];
        s  += v.x + v.y + v.z + v.w;
        ss += v.x * v.x + v.y * v.y + v.z * v.z + v.w * v.w;
    }
    __shared__ float sh[16];
    #pragma unroll
    for (int o = 16; o; o >>= 1) {
        s  += __shfl_xor_sync(0xffffffffu, s, o);
        ss += __shfl_xor_sync(0xffffffffu, ss, o);
    }
    int w = threadIdx.x >> 5;
    if ((threadIdx.x & 31) == 0) { sh[w] = s; sh[8 + w] = ss; }
    __syncthreads();
    if (threadIdx.x == 0) {
        float ts = 0.f, tss = 0.f;
        #pragma unroll
        for (int i = 0; i < 8; i++) { ts += sh[i]; tss += sh[8 + i]; }
        g_part[gi][slab][0] = ts;
        g_part[gi][slab][1] = tss;
    }
}

// ---------------- fused GN-apply + QKV projection (fp32 FFMA 8x8 tiles) -------
// grid (NS/128, BB, 3). z=0: Q from c (g2,b2); z=1: K from x; z=2: V from x.
// 256 threads, thread (ty=tid/16, tx=tid%16) owns 8 outputs x 8 tokens.
#define LDW 132
__global__ void __launch_bounds__(256) qkv_kernel(
    const float* __restrict__ wq, const float* __restrict__ bq,
    const float* __restrict__ wk, const float* __restrict__ bk,
    const float* __restrict__ wv, const float* __restrict__ bv,
    const float* __restrict__ g1, const float* __restrict__ b1,
    const float* __restrict__ g2, const float* __restrict__ b2,
    const float* __restrict__ x,  const float* __restrict__ cin)
{
    extern __shared__ float sm[];
    float* Wt  = sm;                  // [c][o], pad LDW
    float* Ins = sm + CC * LDW;       // [c][tok], pad LDW
    float* SGA = sm + 2 * CC * LDW;   // ga[128]
    float* SGB = SGA + CC;            // be[128]

    int z = blockIdx.z;
    int b = blockIdx.y;
    int n0 = blockIdx.x * 128;
    int which = (z == 0) ? 1 : 0;
    const float* in    = which ? cin : x;
    const float* w     = (z == 0) ? wq : (z == 1 ? wk : wv);
    const float* bias  = (z == 0) ? bq : (z == 1 ? bk : bv);
    const float* gamma = which ? g2 : g1;
    const float* beta  = which ? b2 : b1;
    __nv_bfloat16* out = (z == 0) ? g_qh : (z == 1 ? g_kh : g_vh);

    int tid = threadIdx.x;
    // phase A: ga/be + W load
    if (tid < CC) {
        int ch = tid, g = ch >> 5;
        int gi = which * 8 + b * 4 + g;
        float s = 0.f, ss = 0.f;
        #pragma unroll
        for (int k = 0; k < 8; k++) { s += g_part[gi][k][0]; ss += g_part[gi][k][1]; }
        const float invM = 1.0f / (float)(CG * NS);
        float mean = s * invM;
        float var  = ss * invM - mean * mean;
        float rinv = rsqrtf(var + 1e-6f);
        float ga = gamma[ch] * rinv;
        SGA[ch] = ga;
        SGB[ch] = beta[ch] - mean * ga;
    }
    for (int idx = tid; idx < CC * CC; idx += 256) {
        int o = idx >> 7, c = idx & 127;
        Wt[c * LDW + o] = w[idx];
    }
    __syncthreads();

    // phase B: load + normalize input tile [c][128 tokens]
    for (int idx = tid; idx < CC * 32; idx += 256) {
        int c = idx >> 5, j4 = (idx & 31) * 4;
        float ga = SGA[c], be = SGB[c];
        float4 v = *(const float4*)&in[((size_t)b * CC + c) * NS + n0 + j4];
        v.x = v.x * ga + be; v.y = v.y * ga + be;
        v.z = v.z * ga + be; v.w = v.w * ga + be;
        *(float4*)&Ins[c * LDW + j4] = v;
    }
    __syncthreads();

    int tx = tid & 15, ty = tid >> 4;
    float acc[8][8];
    #pragma unroll
    for (int r = 0; r < 8; r++)
        #pragma unroll
        for (int q = 0; q < 8; q++) acc[r][q] = 0.f;

    #pragma unroll 4
    for (int c = 0; c < CC; c++) {
        float4 w0 = *(const float4*)&Wt[c * LDW + ty * 8];
        float4 w1 = *(const float4*)&Wt[c * LDW + ty * 8 + 4];
        float4 i0 = *(const float4*)&Ins[c * LDW + tx * 8];
        float4 i1 = *(const float4*)&Ins[c * LDW + tx * 8 + 4];
        float wv8[8] = {w0.x, w0.y, w0.z, w0.w, w1.x, w1.y, w1.z, w1.w};
        float iv8[8] = {i0.x, i0.y, i0.z, i0.w, i1.x, i1.y, i1.z, i1.w};
        #pragma unroll
        for (int r = 0; r < 8; r++)
            #pragma unroll
            for (int q = 0; q < 8; q++) acc[r][q] += wv8[r] * iv8[q];
    }

    float sc = (z == 0) ? QSCALE : 1.0f;
    #pragma unroll
    for (int r = 0; r < 8; r++) {
        int o = ty * 8 + r;
        float bv = bias[o];
        uint4 u;
        u.x = pack_bf16((acc[r][0] + bv) * sc, (acc[r][1] + bv) * sc);
        u.y = pack_bf16((acc[r][2] + bv) * sc, (acc[r][3] + bv) * sc);
        u.z = pack_bf16((acc[r][4] + bv) * sc, (acc[r][5] + bv) * sc);
        u.w = pack_bf16((acc[r][6] + bv) * sc, (acc[r][7] + bv) * sc);
        *(uint4*)&out[((size_t)b * CC + o) * NS + n0 + tx * 8] = u;
    }
}

// ---------------- flash attention (bf16 mma, split-KV) ------------------------
// grid (NS/64, BB, SPLIT), 128 threads (4 warps). BM=64, BN=64, d=128.
#define LDB 72
#define SM_TILE (128 * LDB)

__global__ void __launch_bounds__(128, 2) attn_kernel()
{
    extern __shared__ __nv_bfloat16 sh[];
    __nv_bfloat16* Qs = sh;
    __nv_bfloat16* Ksb[2] = { sh + SM_TILE,     sh + 2 * SM_TILE };
    __nv_bfloat16* Vsb[2] = { sh + 3 * SM_TILE, sh + 4 * SM_TILE };

    int b  = blockIdx.y;
    int sp = blockIdx.z;
    int i0 = blockIdx.x * 64;
    int tid = threadIdx.x, lane = tid & 31, warp = tid >> 5;
    int t = lane & 3;
    int m0 = warp * 16;

    const __nv_bfloat16* gq = g_qh + (size_t)b * CC * NS + i0;
    const __nv_bfloat16* gk = g_kh + (size_t)b * CC * NS + sp * JSPAN;
    const __nv_bfloat16* gv = g_vh + (size_t)b * CC * NS + sp * JSPAN;

    for (int idx = tid; idx < 1024; idx += 128) {
        int c = idx >> 3, j8 = (idx & 7) * 8;
        cp16(&Qs[c * LDB + j8], gq + (size_t)c * NS + j8);
        cp16(&Ksb[0][c * LDB + j8], gk + (size_t)c * NS + j8);
        cp16(&Vsb[0][c * LDB + j8], gv + (size_t)c * NS + j8);
    }
    asm volatile("cp.async.commit_group;");
    asm volatile("cp.async.wait_group 0;");
    __syncthreads();

    const int rowA = (lane & 7) + ((lane & 16) ? 8 : 0);
    const int colA = ((lane & 8) ? 8 : 0);
    const int rowK = (lane & 7) + ((lane & 8) ? 8 : 0);
    const int colK = ((lane & 16) ? 8 : 0);

    uint32_t qa[8][4];
    #pragma unroll
    for (int kb = 0; kb < 8; kb++)
        ldsm_x4t(qa[kb], &Qs[(kb * 16 + rowA) * LDB + m0 + colA]);

    float mr0 = -1e30f, mr1 = -1e30f, lr0 = 0.f, lr1 = 0.f;
    float of[16][4];
    #pragma unroll
    for (int nt = 0; nt < 16; nt++)
        #pragma unroll
        for (int e = 0; e < 4; e++) of[nt][e] = 0.f;

    const int NT = JSPAN / 64;
    for (int jt = 0; jt < NT; jt++) {
        const int cur = jt & 1;
        if (jt + 1 < NT) {
            int j0n = (jt + 1) * 64, nb = (jt + 1) & 1;
            for (int idx = tid; idx < 1024; idx += 128) {
                int c = idx >> 3, j8 = (idx & 7) * 8;
                cp16(&Ksb[nb][c * LDB + j8], gk + (size_t)c * NS + j0n + j8);
                cp16(&Vsb[nb][c * LDB + j8], gv + (size_t)c * NS + j0n + j8);
            }
        }
        asm volatile("cp.async.commit_group;");
        asm volatile("cp.async.wait_group 1;");
        __syncthreads();

        const __nv_bfloat16* Ks = Ksb[cur];
        const __nv_bfloat16* Vs = Vsb[cur];

        float sf[8][4];
        #pragma unroll
        for (int nb = 0; nb < 8; nb++)
            #pragma unroll
            for (int e = 0; e < 4; e++) sf[nb][e] = 0.f;

        #pragma unroll
        for (int kb = 0; kb < 8; kb++) {
            #pragma unroll
            for (int nbp = 0; nbp < 4; nbp++) {
                uint32_t kf[4];
                ldsm_x4t(kf, &Ks[(kb * 16 + rowK) * LDB + nbp * 16 + colK]);
                mma16816(sf[2 * nbp],     qa[kb], kf);
                mma16816(sf[2 * nbp + 1], qa[kb], kf + 2);
            }
        }

        float mx0 = -1e30f, mx1 = -1e30f;
        #pragma unroll
        for (int nb = 0; nb < 8; nb++) {
            mx0 = fmaxf(mx0, fmaxf(sf[nb][0], sf[nb][1]));
            mx1 = fmaxf(mx1, fmaxf(sf[nb][2], sf[nb][3]));
        }
        mx0 = fmaxf(mx0, __shfl_xor_sync(0xffffffffu, mx0, 1));
        mx0 = fmaxf(mx0, __shfl_xor_sync(0xffffffffu, mx0, 2));
        mx1 = fmaxf(mx1, __shfl_xor_sync(0xffffffffu, mx1, 1));
        mx1 = fmaxf(mx1, __shfl_xor_sync(0xffffffffu, mx1, 2));

        float mn0 = fmaxf(mr0, mx0), mn1 = fmaxf(mr1, mx1);
        float cr0 = ex2(mr0 - mn0),  cr1 = ex2(mr1 - mn1);
        float rs0 = 0.f, rs1 = 0.f;
        #pragma unroll
        for (int nb = 0; nb < 8; nb++) {
            sf[nb][0] = ex2(sf[nb][0] - mn0);
            sf[nb][1] = ex2(sf[nb][1] - mn0);
            sf[nb][2] = ex2(sf[nb][2] - mn1);
            sf[nb][3] = ex2(sf[nb][3] - mn1);
            rs0 += sf[nb][0] + sf[nb][1];
            rs1 += sf[nb][2] + sf[nb][3];
        }
        rs0 += __shfl_xor_sync(0xffffffffu, rs0, 1);
        rs0 += __shfl_xor_sync(0xffffffffu, rs0, 2);
        rs1 += __shfl_xor_sync(0xffffffffu, rs1, 1);
        rs1 += __shfl_xor_sync(0xffffffffu, rs1, 2);
        lr0 = lr0 * cr0 + rs0;
        lr1 = lr1 * cr1 + rs1;
        mr0 = mn0; mr1 = mn1;

        #pragma unroll
        for (int nt = 0; nt < 16; nt++) {
            of[nt][0] *= cr0; of[nt][1] *= cr0;
            of[nt][2] *= cr1; of[nt][3] *= cr1;
        }

        uint32_t pa[4][4];
        #pragma unroll
        for (int kt = 0; kt < 4; kt++) {
            pa[kt][0] = pack_bf16(sf[2 * kt][0],     sf[2 * kt][1]);
            pa[kt][1] = pack_bf16(sf[2 * kt][2],     sf[2 * kt][3]);
            pa[kt][2] = pack_bf16(sf[2 * kt + 1][0], sf[2 * kt + 1][1]);
            pa[kt][3] = pack_bf16(sf[2 * kt + 1][2], sf[2 * kt + 1][3]);
        }

        #pragma unroll
        for (int ntp = 0; ntp < 8; ntp++) {
            #pragma unroll
            for (int kt = 0; kt < 4; kt++) {
                uint32_t vf[4];
                ldsm_x4(vf, &Vs[(ntp * 16 + rowA) * LDB + kt * 16 + colA]);
                mma16816(of[2 * ntp],     pa[kt], vf);
                mma16816(of[2 * ntp + 1], pa[kt], vf + 2);
            }
        }
        __syncthreads();
    }

    // epilogue: write UNNORMALIZED partials + m/l
    int ig = i0 + m0 + (lane >> 2);
    float* po = g_po + ((size_t)(sp * BB + b)) * CC * NS;
    #pragma unroll
    for (int nt = 0; nt < 16; nt++) {
        int c = 8 * nt + 2 * t;
        po[(size_t)c * NS + ig]           = of[nt][0];
        po[(size_t)(c + 1) * NS + ig]     = of[nt][1];
        po[(size_t)c * NS + ig + 8]       = of[nt][2];
        po[(size_t)(c + 1) * NS + ig + 8] = of[nt][3];
    }
    if (t == 0) {
        size_t mb = (size_t)(sp * BB + b) * NS;
        g_pm[mb + ig]     = mr0;
        g_pm[mb + ig + 8] = mr1;
        g_pl[mb + ig]     = lr0;
        g_pl[mb + ig + 8] = lr1;
    }
}

// ---------------- fused split-combine + output projection + residual ----------
// grid (NS/128, BB), 256 threads, 8x8 register tiles.
__global__ void __launch_bounds__(256) proj_out_kernel(
    const float* __restrict__ w, const float* __restrict__ bias,
    const float* __restrict__ xres, float* __restrict__ out)
{
    extern __shared__ float sm[];
    float* Wt  = sm;
    float* Ins = sm + CC * LDW;
    float* A0  = sm + 2 * CC * LDW;   // per-token combine weight, split 0
    float* A1  = A0 + 128;            // split 1

    int b  = blockIdx.y;
    int n0 = blockIdx.x * 128;
    int tid = threadIdx.x;

    if (tid < 128) {
        int i = n0 + tid;
        float m0v = g_pm[(size_t)b * NS + i];
        float m1v = g_pm[(size_t)(BB + b) * NS + i];
        float l0v = g_pl[(size_t)b * NS + i];
        float l1v = g_pl[(size_t)(BB + b) * NS + i];
        float mm = fmaxf(m0v, m1v);
        float w0 = ex2(m0v - mm), w1 = ex2(m1v - mm);
        float invl = 1.0f / (l0v * w0 + l1v * w1);
        A0[tid] = w0 * invl;
        A1[tid] = w1 * invl;
    }
    for (int idx = tid; idx < CC * CC; idx += 256) {
        int o = idx >> 7, c = idx & 127;
        Wt[c * LDW + o] = w[idx];
    }
    __syncthreads();

    // combine partials into Ins[c][j]
    const float* po0 = g_po + (size_t)b * CC * NS;
    const float* po1 = g_po + (size_t)(BB + b) * CC * NS;
    for (int idx = tid; idx < CC * 32; idx += 256) {
        int c = idx >> 5, j4 = (idx & 31) * 4;
        float4 p0 = *(const float4*)&po0[(size_t)c * NS + n0 + j4];
        float4 p1 = *(const float4*)&po1[(size_t)c * NS + n0 + j4];
        float4 r;
        r.x = p0.x * A0[j4]     + p1.x * A1[j4];
        r.y = p0.y * A0[j4 + 1] + p1.y * A1[j4 + 1];
        r.z = p0.z * A0[j4 + 2] + p1.z * A1[j4 + 2];
        r.w = p0.w * A0[j4 + 3] + p1.w * A1[j4 + 3];
        *(float4*)&Ins[c * LDW + j4] = r;
    }
    __syncthreads();

    int tx = tid & 15, ty = tid >> 4;
    float acc[8][8];
    #pragma unroll
    for (int r = 0; r < 8; r++)
        #pragma unroll
        for (int q = 0; q < 8; q++) acc[r][q] = 0.f;

    #pragma unroll 4
    for (int c = 0; c < CC; c++) {
        float4 w0 = *(const float4*)&Wt[c * LDW + ty * 8];
        float4 w1 = *(const float4*)&Wt[c * LDW + ty * 8 + 4];
        float4 i0 = *(const float4*)&Ins[c * LDW + tx * 8];
        float4 i1 = *(const float4*)&Ins[c * LDW + tx * 8 + 4];
        float wv8[8] = {w0.x, w0.y, w0.z, w0.w, w1.x, w1.y, w1.z, w1.w};
        float iv8[8] = {i0.x, i0.y, i0.z, i0.w, i1.x, i1.y, i1.z, i1.w};
        #pragma unroll
        for (int r = 0; r < 8; r++)
            #pragma unroll
            for (int q = 0; q < 8; q++) acc[r][q] += wv8[r] * iv8[q];
    }

    #pragma unroll
    for (int r = 0; r < 8; r++) {
        int o = ty * 8 + r;
        float bv = bias[o];
        size_t base = ((size_t)b * CC + o) * NS + n0 + tx * 8;
        float4 x0 = *(const float4*)&xres[base];
        float4 x1 = *(const float4*)&xres[base + 4];
        float4 r0, r1;
        r0.x = acc[r][0] + bv + x0.x; r0.y = acc[r][1] + bv + x0.y;
        r0.z = acc[r][2] + bv + x0.z; r0.w = acc[r][3] + bv + x0.w;
        r1.x = acc[r][4] + bv + x1.x; r1.y = acc[r][5] + bv + x1.y;
        r1.z = acc[r][6] + bv + x1.z; r1.w = acc[r][7] + bv + x1.w;
        *(float4*)&out[base]     = r0;
        *(float4*)&out[base + 4] = r1;
    }
}

// ---------------- launcher ---------------------------------------------------
extern "C" void kernel_launch(void* const* d_in, const int* in_sizes, int n_in,
                              void* d_out, int out_size)
{
    const float* x  = (const float*)d_in[0];
    const float* c  = (const float*)d_in[1];
    const float* g1 = (const float*)d_in[2];
    const float* b1 = (const float*)d_in[3];
    const float* g2 = (const float*)d_in[4];
    const float* b2 = (const float*)d_in[5];
    const float* wq = (const float*)d_in[6];
    const float* bq = (const float*)d_in[7];
    const float* wk = (const float*)d_in[8];
    const float* bk = (const float*)d_in[9];
    const float* wv = (const float*)d_in[10];
    const float* bv = (const float*)d_in[11];
    const float* wp = (const float*)d_in[12];
    const float* bp = (const float*)d_in[13];
    float* out = (float*)d_out;

    const int GEMM_SMEM = (2 * CC * LDW + 256) * 4;     // 136192 B
    const int ATTN_SMEM = 5 * SM_TILE * 2;              // 92160 B
    cudaFuncSetAttribute(qkv_kernel,      cudaFuncAttributeMaxDynamicSharedMemorySize, GEMM_SMEM);
    cudaFuncSetAttribute(proj_out_kernel, cudaFuncAttributeMaxDynamicSharedMemorySize, GEMM_SMEM);
    cudaFuncSetAttribute(attn_kernel,     cudaFuncAttributeMaxDynamicSharedMemorySize, ATTN_SMEM);

    gn_stats_kernel<<<dim3(8, 16), 256>>>(x, c);

    dim3 gq(NS / 128, BB, 3);
    qkv_kernel<<<gq, 256, GEMM_SMEM>>>(wq, bq, wk, bk, wv, bv,
                                       g1, b1, g2, b2, x, c);

    dim3 ga(NS / 64, BB, SPLIT);
    attn_kernel<<<ga, 128, ATTN_SMEM>>>();

    dim3 gp(NS / 128, BB);
    proj_out_kernel<<<gp, 256, GEMM_SMEM>>>(wp, bp, x, out);
}

// round 4
// speedup vs baseline: 10.2597x; 1.4223x over previous
#include <cuda_runtime.h>
#include <cuda_bf16.h>
#include <math.h>
#include <stdint.h>

// Problem constants
#define BB 2
#define CC 128
#define GG 4
#define CG 32
#define NS 4096
#define SPLIT 2
#define JSPAN (NS / SPLIT)
// 128^-0.5 * log2(e): fold into Q so softmax works in exp2 domain
#define QSCALE 0.12751744154339495f

// ---------------- scratch (device globals) ----------------------------------
__device__ __nv_bfloat16 g_qh[BB * CC * NS];   // Q * QSCALE, bf16, [b][c][n]
__device__ __nv_bfloat16 g_kh[BB * CC * NS];
__device__ __nv_bfloat16 g_vh[BB * CC * NS];
__device__ float g_po[SPLIT * BB * CC * NS];   // unnormalized partial O
__device__ float g_pm[SPLIT * BB * NS];        // partial row max (log2 domain)
__device__ float g_pl[SPLIT * BB * NS];        // partial row sum
__device__ float g_part[16][8][2];             // GN partials [group][slab][sum,ssq]

// ---------------- asm helpers -------------------------------------------------
__device__ __forceinline__ float ex2(float x) {
    float r; asm("ex2.approx.ftz.f32 %0, %1;" : "=f"(r) : "f"(x)); return r;
}
__device__ __forceinline__ uint32_t pack_bf16(float lo, float hi) {
    uint32_t d;
    asm("cvt.rn.bf16x2.f32 %0, %1, %2;" : "=r"(d) : "f"(hi), "f"(lo));
    return d;
}
__device__ __forceinline__ void cp16(void* dst_smem, const void* src) {
    uint32_t d = (uint32_t)__cvta_generic_to_shared(dst_smem);
    asm volatile("cp.async.cg.shared.global [%0], [%1], 16;\n" :: "r"(d), "l"(src));
}
__device__ __forceinline__ void ldsm_x4(uint32_t* r, const void* p) {
    uint32_t a = (uint32_t)__cvta_generic_to_shared(p);
    asm volatile("ldmatrix.sync.aligned.m8n8.x4.shared.b16 {%0,%1,%2,%3}, [%4];"
        : "=r"(r[0]), "=r"(r[1]), "=r"(r[2]), "=r"(r[3]) : "r"(a));
}
__device__ __forceinline__ void ldsm_x4t(uint32_t* r, const void* p) {
    uint32_t a = (uint32_t)__cvta_generic_to_shared(p);
    asm volatile("ldmatrix.sync.aligned.m8n8.x4.trans.shared.b16 {%0,%1,%2,%3}, [%4];"
        : "=r"(r[0]), "=r"(r[1]), "=r"(r[2]), "=r"(r[3]) : "r"(a));
}
__device__ __forceinline__ void mma16816(float* d, const uint32_t* a, const uint32_t* b) {
    asm volatile(
        "mma.sync.aligned.m16n8k16.row.col.f32.bf16.bf16.f32 "
        "{%0,%1,%2,%3},{%4,%5,%6,%7},{%8,%9},{%0,%1,%2,%3};"
        : "+f"(d[0]), "+f"(d[1]), "+f"(d[2]), "+f"(d[3])
        : "r"(a[0]), "r"(a[1]), "r"(a[2]), "r"(a[3]), "r"(b[0]), "r"(b[1]));
}

// ---------------- GroupNorm partial stats -------------------------------------
__global__ void __launch_bounds__(256) gn_stats_kernel(
    const float* __restrict__ x, const float* __restrict__ c)
{
    int slab = blockIdx.x;
    int gi   = blockIdx.y;
    int which = gi >> 3, b = (gi >> 2) & 1, g = gi & 3;
    const float* in = which ? c : x;
    const float4* p4 = (const float4*)(in + ((size_t)(b * CC + g * CG)) * NS) +
                       (size_t)slab * 4096;

    float s = 0.f, ss = 0.f;
    #pragma unroll 4
    for (int i = threadIdx.x; i < 4096; i += 256) {
        float4 v = p4[i];
        s  += v.x + v.y + v.z + v.w;
        ss += v.x * v.x + v.y * v.y + v.z * v.z + v.w * v.w;
    }
    __shared__ float sh[16];
    #pragma unroll
    for (int o = 16; o; o >>= 1) {
        s  += __shfl_xor_sync(0xffffffffu, s, o);
        ss += __shfl_xor_sync(0xffffffffu, ss, o);
    }
    int w = threadIdx.x >> 5;
    if ((threadIdx.x & 31) == 0) { sh[w] = s; sh[8 + w] = ss; }
    __syncthreads();
    if (threadIdx.x == 0) {
        float ts = 0.f, tss = 0.f;
        #pragma unroll
        for (int i = 0; i < 8; i++) { ts += sh[i]; tss += sh[8 + i]; }
        g_part[gi][slab][0] = ts;
        g_part[gi][slab][1] = tss;
    }
}

// ---------------- fused GN-apply + QKV projection (bf16 tensor-core) ----------
// grid (NS/128, BB, 3). 256 threads = 8 warps; warp w owns out rows w*16..w*16+15.
// O[o,n] = sum_c W[o,c] * GN(in)[c,n]; M=128, N=128 tok, K=128.
#define LDWB 136   // bf16 row pitch for W [o][c] (272B, odd 16B multiple)
#define LDIB 136   // bf16 row pitch for In [c][n]
__global__ void __launch_bounds__(256) qkv_kernel(
    const float* __restrict__ wq, const float* __restrict__ bq,
    const float* __restrict__ wk, const float* __restrict__ bk,
    const float* __restrict__ wv, const float* __restrict__ bv,
    const float* __restrict__ g1, const float* __restrict__ b1,
    const float* __restrict__ g2, const float* __restrict__ b2,
    const float* __restrict__ x,  const float* __restrict__ cin)
{
    extern __shared__ char smraw[];
    __nv_bfloat16* Wb = (__nv_bfloat16*)smraw;                 // [128][LDWB]
    __nv_bfloat16* In = Wb + CC * LDWB;                        // [128][LDIB]
    float* SGA = (float*)(In + CC * LDIB);                     // ga[128]
    float* SGB = SGA + CC;                                     // be[128]

    int z = blockIdx.z;
    int b = blockIdx.y;
    int n0 = blockIdx.x * 128;
    int which = (z == 0) ? 1 : 0;
    const float* in    = which ? cin : x;
    const float* w     = (z == 0) ? wq : (z == 1 ? wk : wv);
    const float* bias  = (z == 0) ? bq : (z == 1 ? bk : bv);
    const float* gamma = which ? g2 : g1;
    const float* beta  = which ? b2 : b1;
    __nv_bfloat16* out = (z == 0) ? g_qh : (z == 1 ? g_kh : g_vh);

    int tid = threadIdx.x;
    if (tid < CC) {
        int ch = tid, g = ch >> 5;
        int gi = which * 8 + b * 4 + g;
        float s = 0.f, ss = 0.f;
        #pragma unroll
        for (int k = 0; k < 8; k++) { s += g_part[gi][k][0]; ss += g_part[gi][k][1]; }
        const float invM = 1.0f / (float)(CG * NS);
        float mean = s * invM;
        float var  = ss * invM - mean * mean;
        float rinv = rsqrtf(var + 1e-6f);
        float ga = gamma[ch] * rinv;
        SGA[ch] = ga;
        SGB[ch] = beta[ch] - mean * ga;
    }
    // W fp32 -> bf16 smem [o][c]
    for (int idx = tid; idx < CC * CC / 2; idx += 256) {
        int o = idx >> 6, kp = idx & 63;                // kp: pair of c
        float2 w2 = *(const float2*)&w[o * CC + kp * 2];
        ((uint32_t*)&Wb[o * LDWB])[kp] = pack_bf16(w2.x, w2.y);
    }
    __syncthreads();
    // input tile: load fp32, normalize, convert bf16 -> In[c][n]
    for (int idx = tid; idx < CC * 32; idx += 256) {
        int c = idx >> 5, n4 = (idx & 31) * 4;
        float ga = SGA[c], be = SGB[c];
        float4 v = *(const float4*)&in[((size_t)b * CC + c) * NS + n0 + n4];
        uint32_t* dst = (uint32_t*)&In[c * LDIB + n4];
        dst[0] = pack_bf16(v.x * ga + be, v.y * ga + be);
        dst[1] = pack_bf16(v.z * ga + be, v.w * ga + be);
    }
    __syncthreads();

    int lane = tid & 31, warp = tid >> 5;
    int m0 = warp * 16;
    const int rowK = (lane & 7) + ((lane & 8) ? 8 : 0);
    const int colK = ((lane & 16) ? 8 : 0);

    float acc[16][4];
    #pragma unroll
    for (int nf = 0; nf < 16; nf++)
        #pragma unroll
        for (int e = 0; e < 4; e++) acc[nf][e] = 0.f;

    #pragma unroll
    for (int kb = 0; kb < 8; kb++) {
        uint32_t aw[4];
        ldsm_x4(aw, &Wb[(m0 + rowK) * LDWB + kb * 16 + colK]);
        #pragma unroll
        for (int nb = 0; nb < 8; nb++) {
            uint32_t bf[4];
            ldsm_x4t(bf, &In[(kb * 16 + rowK) * LDIB + nb * 16 + colK]);
            mma16816(acc[2 * nb],     aw, bf);
            mma16816(acc[2 * nb + 1], aw, bf + 2);
        }
    }

    float sc = (z == 0) ? QSCALE : 1.0f;
    int orow = m0 + (lane >> 2);
    int ncol = (lane & 3) * 2;
    float bv0 = bias[orow], bv1 = bias[orow + 8];
    size_t ob0 = ((size_t)b * CC + orow) * NS + n0;
    size_t ob1 = ob0 + (size_t)8 * NS;
    #pragma unroll
    for (int nf = 0; nf < 16; nf++) {
        int n = nf * 8 + ncol;
        *(uint32_t*)&out[ob0 + n] =
            pack_bf16((acc[nf][0] + bv0) * sc, (acc[nf][1] + bv0) * sc);
        *(uint32_t*)&out[ob1 + n] =
            pack_bf16((acc[nf][2] + bv1) * sc, (acc[nf][3] + bv1) * sc);
    }
}

// ---------------- flash attention (bf16 mma, split-KV) ------------------------
#define LDB 72
#define SM_TILE (128 * LDB)

__global__ void __launch_bounds__(128, 2) attn_kernel()
{
    extern __shared__ __nv_bfloat16 sh[];
    __nv_bfloat16* Qs = sh;
    __nv_bfloat16* Ksb[2] = { sh + SM_TILE,     sh + 2 * SM_TILE };
    __nv_bfloat16* Vsb[2] = { sh + 3 * SM_TILE, sh + 4 * SM_TILE };

    int b  = blockIdx.y;
    int sp = blockIdx.z;
    int i0 = blockIdx.x * 64;
    int tid = threadIdx.x, lane = tid & 31, warp = tid >> 5;
    int t = lane & 3;
    int m0 = warp * 16;

    const __nv_bfloat16* gq = g_qh + (size_t)b * CC * NS + i0;
    const __nv_bfloat16* gk = g_kh + (size_t)b * CC * NS + sp * JSPAN;
    const __nv_bfloat16* gv = g_vh + (size_t)b * CC * NS + sp * JSPAN;

    for (int idx = tid; idx < 1024; idx += 128) {
        int c = idx >> 3, j8 = (idx & 7) * 8;
        cp16(&Qs[c * LDB + j8], gq + (size_t)c * NS + j8);
        cp16(&Ksb[0][c * LDB + j8], gk + (size_t)c * NS + j8);
        cp16(&Vsb[0][c * LDB + j8], gv + (size_t)c * NS + j8);
    }
    asm volatile("cp.async.commit_group;");
    asm volatile("cp.async.wait_group 0;");
    __syncthreads();

    const int rowA = (lane & 7) + ((lane & 16) ? 8 : 0);
    const int colA = ((lane & 8) ? 8 : 0);
    const int rowK = (lane & 7) + ((lane & 8) ? 8 : 0);
    const int colK = ((lane & 16) ? 8 : 0);

    uint32_t qa[8][4];
    #pragma unroll
    for (int kb = 0; kb < 8; kb++)
        ldsm_x4t(qa[kb], &Qs[(kb * 16 + rowA) * LDB + m0 + colA]);

    float mr0 = -1e30f, mr1 = -1e30f, lr0 = 0.f, lr1 = 0.f;
    float of[16][4];
    #pragma unroll
    for (int nt = 0; nt < 16; nt++)
        #pragma unroll
        for (int e = 0; e < 4; e++) of[nt][e] = 0.f;

    const int NT = JSPAN / 64;
    for (int jt = 0; jt < NT; jt++) {
        const int cur = jt & 1;
        if (jt + 1 < NT) {
            int j0n = (jt + 1) * 64, nb = (jt + 1) & 1;
            for (int idx = tid; idx < 1024; idx += 128) {
                int c = idx >> 3, j8 = (idx & 7) * 8;
                cp16(&Ksb[nb][c * LDB + j8], gk + (size_t)c * NS + j0n + j8);
                cp16(&Vsb[nb][c * LDB + j8], gv + (size_t)c * NS + j0n + j8);
            }
        }
        asm volatile("cp.async.commit_group;");
        asm volatile("cp.async.wait_group 1;");
        __syncthreads();

        const __nv_bfloat16* Ks = Ksb[cur];
        const __nv_bfloat16* Vs = Vsb[cur];

        float sf[8][4];
        #pragma unroll
        for (int nb = 0; nb < 8; nb++)
            #pragma unroll
            for (int e = 0; e < 4; e++) sf[nb][e] = 0.f;

        #pragma unroll
        for (int kb = 0; kb < 8; kb++) {
            #pragma unroll
            for (int nbp = 0; nbp < 4; nbp++) {
                uint32_t kf[4];
                ldsm_x4t(kf, &Ks[(kb * 16 + rowK) * LDB + nbp * 16 + colK]);
                mma16816(sf[2 * nbp],     qa[kb], kf);
                mma16816(sf[2 * nbp + 1], qa[kb], kf + 2);
            }
        }

        float mx0 = -1e30f, mx1 = -1e30f;
        #pragma unroll
        for (int nb = 0; nb < 8; nb++) {
            mx0 = fmaxf(mx0, fmaxf(sf[nb][0], sf[nb][1]));
            mx1 = fmaxf(mx1, fmaxf(sf[nb][2], sf[nb][3]));
        }
        mx0 = fmaxf(mx0, __shfl_xor_sync(0xffffffffu, mx0, 1));
        mx0 = fmaxf(mx0, __shfl_xor_sync(0xffffffffu, mx0, 2));
        mx1 = fmaxf(mx1, __shfl_xor_sync(0xffffffffu, mx1, 1));
        mx1 = fmaxf(mx1, __shfl_xor_sync(0xffffffffu, mx1, 2));

        float mn0 = fmaxf(mr0, mx0), mn1 = fmaxf(mr1, mx1);
        float cr0 = ex2(mr0 - mn0),  cr1 = ex2(mr1 - mn1);
        float rs0 = 0.f, rs1 = 0.f;
        #pragma unroll
        for (int nb = 0; nb < 8; nb++) {
            sf[nb][0] = ex2(sf[nb][0] - mn0);
            sf[nb][1] = ex2(sf[nb][1] - mn0);
            sf[nb][2] = ex2(sf[nb][2] - mn1);
            sf[nb][3] = ex2(sf[nb][3] - mn1);
            rs0 += sf[nb][0] + sf[nb][1];
            rs1 += sf[nb][2] + sf[nb][3];
        }
        rs0 += __shfl_xor_sync(0xffffffffu, rs0, 1);
        rs0 += __shfl_xor_sync(0xffffffffu, rs0, 2);
        rs1 += __shfl_xor_sync(0xffffffffu, rs1, 1);
        rs1 += __shfl_xor_sync(0xffffffffu, rs1, 2);
        lr0 = lr0 * cr0 + rs0;
        lr1 = lr1 * cr1 + rs1;
        mr0 = mn0; mr1 = mn1;

        #pragma unroll
        for (int nt = 0; nt < 16; nt++) {
            of[nt][0] *= cr0; of[nt][1] *= cr0;
            of[nt][2] *= cr1; of[nt][3] *= cr1;
        }

        uint32_t pa[4][4];
        #pragma unroll
        for (int kt = 0; kt < 4; kt++) {
            pa[kt][0] = pack_bf16(sf[2 * kt][0],     sf[2 * kt][1]);
            pa[kt][1] = pack_bf16(sf[2 * kt][2],     sf[2 * kt][3]);
            pa[kt][2] = pack_bf16(sf[2 * kt + 1][0], sf[2 * kt + 1][1]);
            pa[kt][3] = pack_bf16(sf[2 * kt + 1][2], sf[2 * kt + 1][3]);
        }

        #pragma unroll
        for (int ntp = 0; ntp < 8; ntp++) {
            #pragma unroll
            for (int kt = 0; kt < 4; kt++) {
                uint32_t vf[4];
                ldsm_x4(vf, &Vs[(ntp * 16 + rowA) * LDB + kt * 16 + colA]);
                mma16816(of[2 * ntp],     pa[kt], vf);
                mma16816(of[2 * ntp + 1], pa[kt], vf + 2);
            }
        }
        __syncthreads();
    }

    int ig = i0 + m0 + (lane >> 2);
    float* po = g_po + ((size_t)(sp * BB + b)) * CC * NS;
    #pragma unroll
    for (int nt = 0; nt < 16; nt++) {
        int c = 8 * nt + 2 * t;
        po[(size_t)c * NS + ig]           = of[nt][0];
        po[(size_t)(c + 1) * NS + ig]     = of[nt][1];
        po[(size_t)c * NS + ig + 8]       = of[nt][2];
        po[(size_t)(c + 1) * NS + ig + 8] = of[nt][3];
    }
    if (t == 0) {
        size_t mb = (size_t)(sp * BB + b) * NS;
        g_pm[mb + ig]     = mr0;
        g_pm[mb + ig + 8] = mr1;
        g_pl[mb + ig]     = lr0;
        g_pl[mb + ig + 8] = lr1;
    }
}

// ---------------- fused split-combine + output projection (bf16 mma) ----------
// grid (NS/64, BB), 256 threads. M=128 out, N=64 tok, K=128.
#define LDPI 72
__global__ void __launch_bounds__(256) proj_out_kernel(
    const float* __restrict__ w, const float* __restrict__ bias,
    const float* __restrict__ xres, float* __restrict__ out)
{
    extern __shared__ char smraw[];
    __nv_bfloat16* Wb = (__nv_bfloat16*)smraw;                 // [128][LDWB]
    __nv_bfloat16* In = Wb + CC * LDWB;                        // [128][LDPI]
    float* A0 = (float*)(In + CC * LDPI);                      // [64]
    float* A1 = A0 + 64;

    int b  = blockIdx.y;
    int n0 = blockIdx.x * 64;
    int tid = threadIdx.x;

    if (tid < 64) {
        int i = n0 + tid;
        float m0v = g_pm[(size_t)b * NS + i];
        float m1v = g_pm[(size_t)(BB + b) * NS + i];
        float l0v = g_pl[(size_t)b * NS + i];
        float l1v = g_pl[(size_t)(BB + b) * NS + i];
        float mm = fmaxf(m0v, m1v);
        float w0 = ex2(m0v - mm), w1 = ex2(m1v - mm);
        float invl = 1.0f / (l0v * w0 + l1v * w1);
        A0[tid] = w0 * invl;
        A1[tid] = w1 * invl;
    }
    for (int idx = tid; idx < CC * CC / 2; idx += 256) {
        int o = idx >> 6, kp = idx & 63;
        float2 w2 = *(const float2*)&w[o * CC + kp * 2];
        ((uint32_t*)&Wb[o * LDWB])[kp] = pack_bf16(w2.x, w2.y);
    }
    __syncthreads();

    const float* po0 = g_po + (size_t)b * CC * NS;
    const float* po1 = g_po + (size_t)(BB + b) * CC * NS;
    for (int idx = tid; idx < CC * 16; idx += 256) {
        int c = idx >> 4, n4 = (idx & 15) * 4;
        float4 p0 = *(const float4*)&po0[(size_t)c * NS + n0 + n4];
        float4 p1 = *(const float4*)&po1[(size_t)c * NS + n0 + n4];
        float r0 = p0.x * A0[n4]     + p1.x * A1[n4];
        float r1 = p0.y * A0[n4 + 1] + p1.y * A1[n4 + 1];
        float r2 = p0.z * A0[n4 + 2] + p1.z * A1[n4 + 2];
        float r3 = p0.w * A0[n4 + 3] + p1.w * A1[n4 + 3];
        uint32_t* dst = (uint32_t*)&In[c * LDPI + n4];
        dst[0] = pack_bf16(r0, r1);
        dst[1] = pack_bf16(r2, r3);
    }
    __syncthreads();

    int lane = tid & 31, warp = tid >> 5;
    int m0 = warp * 16;
    const int rowK = (lane & 7) + ((lane & 8) ? 8 : 0);
    const int colK = ((lane & 16) ? 8 : 0);

    float acc[8][4];
    #pragma unroll
    for (int nf = 0; nf < 8; nf++)
        #pragma unroll
        for (int e = 0; e < 4; e++) acc[nf][e] = 0.f;

    #pragma unroll
    for (int kb = 0; kb < 8; kb++) {
        uint32_t aw[4];
        ldsm_x4(aw, &Wb[(m0 + rowK) * LDWB + kb * 16 + colK]);
        #pragma unroll
        for (int nb = 0; nb < 4; nb++) {
            uint32_t bf[4];
            ldsm_x4t(bf, &In[(kb * 16 + rowK) * LDPI + nb * 16 + colK]);
            mma16816(acc[2 * nb],     aw, bf);
            mma16816(acc[2 * nb + 1], aw, bf + 2);
        }
    }

    int orow = m0 + (lane >> 2);
    int ncol = (lane & 3) * 2;
    float bv0 = bias[orow], bv1 = bias[orow + 8];
    size_t ob0 = ((size_t)b * CC + orow) * NS + n0;
    size_t ob1 = ob0 + (size_t)8 * NS;
    #pragma unroll
    for (int nf = 0; nf < 8; nf++) {
        int n = nf * 8 + ncol;
        float2 x0 = *(const float2*)&xres[ob0 + n];
        float2 x1 = *(const float2*)&xres[ob1 + n];
        float2 r0 = { acc[nf][0] + bv0 + x0.x, acc[nf][1] + bv0 + x0.y };
        float2 r1 = { acc[nf][2] + bv1 + x1.x, acc[nf][3] + bv1 + x1.y };
        *(float2*)&out[ob0 + n] = r0;
        *(float2*)&out[ob1 + n] = r1;
    }
}

// ---------------- launcher ---------------------------------------------------
extern "C" void kernel_launch(void* const* d_in, const int* in_sizes, int n_in,
                              void* d_out, int out_size)
{
    const float* x  = (const float*)d_in[0];
    const float* c  = (const float*)d_in[1];
    const float* g1 = (const float*)d_in[2];
    const float* b1 = (const float*)d_in[3];
    const float* g2 = (const float*)d_in[4];
    const float* b2 = (const float*)d_in[5];
    const float* wq = (const float*)d_in[6];
    const float* bq = (const float*)d_in[7];
    const float* wk = (const float*)d_in[8];
    const float* bk = (const float*)d_in[9];
    const float* wv = (const float*)d_in[10];
    const float* bv = (const float*)d_in[11];
    const float* wp = (const float*)d_in[12];
    const float* bp = (const float*)d_in[13];
    float* out = (float*)d_out;

    const int QKV_SMEM  = (CC * LDWB + CC * LDIB) * 2 + 2 * CC * 4;   // 70656
    const int PROJ_SMEM = (CC * LDWB + CC * LDPI) * 2 + 2 * 64 * 4;   // 53760
    const int ATTN_SMEM = 5 * SM_TILE * 2;                            // 92160
    cudaFuncSetAttribute(qkv_kernel,      cudaFuncAttributeMaxDynamicSharedMemorySize, QKV_SMEM);
    cudaFuncSetAttribute(proj_out_kernel, cudaFuncAttributeMaxDynamicSharedMemorySize, PROJ_SMEM);
    cudaFuncSetAttribute(attn_kernel,     cudaFuncAttributeMaxDynamicSharedMemorySize, ATTN_SMEM);

    gn_stats_kernel<<<dim3(8, 16), 256>>>(x, c);

    dim3 gq(NS / 128, BB, 3);
    qkv_kernel<<<gq, 256, QKV_SMEM>>>(wq, bq, wk, bk, wv, bv,
                                      g1, b1, g2, b2, x, c);

    dim3 ga(NS / 64, BB, SPLIT);
    attn_kernel<<<ga, 128, ATTN_SMEM>>>();

    dim3 gp(NS / 64, BB);
    proj_out_kernel<<<gp, 256, PROJ_SMEM>>>(wp, bp, x, out);
}

// round 5
// speedup vs baseline: 10.4952x; 1.0230x over previous
#include <cuda_runtime.h>
#include <cuda_bf16.h>
#include <math.h>
#include <stdint.h>

// Problem constants
#define BB 2
#define CC 128
#define GG 4
#define CG 32
#define NS 4096
#define SPLIT 2
#define JSPAN (NS / SPLIT)
// 128^-0.5 * log2(e): fold into Q so softmax works in exp2 domain
#define QSCALE 0.12751744154339495f

// ---------------- scratch (device globals) ----------------------------------
__device__ __nv_bfloat16 g_qh[BB * CC * NS];    // Q * QSCALE, bf16, [b][c][n]
__device__ __nv_bfloat16 g_kh[BB * CC * NS];
__device__ __nv_bfloat16 g_vh[BB * CC * NS];
__device__ __nv_bfloat16 g_pob[SPLIT * BB * NS * CC]; // per-split normalized O, [sp][b][n][c]
__device__ float g_pm[SPLIT * BB * NS];         // partial row max (log2 domain)
__device__ float g_pl[SPLIT * BB * NS];         // partial row sum
__device__ float g_part[16][8][2];              // GN partials [group][slab][sum,ssq]

// ---------------- asm helpers -------------------------------------------------
__device__ __forceinline__ float ex2(float x) {
    float r; asm("ex2.approx.ftz.f32 %0, %1;" : "=f"(r) : "f"(x)); return r;
}
__device__ __forceinline__ uint32_t pack_bf16(float lo, float hi) {
    uint32_t d;
    asm("cvt.rn.bf16x2.f32 %0, %1, %2;" : "=r"(d) : "f"(hi), "f"(lo));
    return d;
}
__device__ __forceinline__ void cp16(void* dst_smem, const void* src) {
    uint32_t d = (uint32_t)__cvta_generic_to_shared(dst_smem);
    asm volatile("cp.async.cg.shared.global [%0], [%1], 16;\n" :: "r"(d), "l"(src));
}
__device__ __forceinline__ void ldsm_x4(uint32_t* r, const void* p) {
    uint32_t a = (uint32_t)__cvta_generic_to_shared(p);
    asm volatile("ldmatrix.sync.aligned.m8n8.x4.shared.b16 {%0,%1,%2,%3}, [%4];"
        : "=r"(r[0]), "=r"(r[1]), "=r"(r[2]), "=r"(r[3]) : "r"(a));
}
__device__ __forceinline__ void ldsm_x4t(uint32_t* r, const void* p) {
    uint32_t a = (uint32_t)__cvta_generic_to_shared(p);
    asm volatile("ldmatrix.sync.aligned.m8n8.x4.trans.shared.b16 {%0,%1,%2,%3}, [%4];"
        : "=r"(r[0]), "=r"(r[1]), "=r"(r[2]), "=r"(r[3]) : "r"(a));
}
__device__ __forceinline__ void mma16816(float* d, const uint32_t* a, const uint32_t* b) {
    asm volatile(
        "mma.sync.aligned.m16n8k16.row.col.f32.bf16.bf16.f32 "
        "{%0,%1,%2,%3},{%4,%5,%6,%7},{%8,%9},{%0,%1,%2,%3};"
        : "+f"(d[0]), "+f"(d[1]), "+f"(d[2]), "+f"(d[3])
        : "r"(a[0]), "r"(a[1]), "r"(a[2]), "r"(a[3]), "r"(b[0]), "r"(b[1]));
}

// ---------------- GroupNorm partial stats -------------------------------------
__global__ void __launch_bounds__(256) gn_stats_kernel(
    const float* __restrict__ x, const float* __restrict__ c)
{
    int slab = blockIdx.x;
    int gi   = blockIdx.y;
    int which = gi >> 3, b = (gi >> 2) & 1, g = gi & 3;
    const float* in = which ? c : x;
    const float4* p4 = (const float4*)(in + ((size_t)(b * CC + g * CG)) * NS) +
                       (size_t)slab * 4096;

    float s = 0.f, ss = 0.f;
    #pragma unroll 4
    for (int i = threadIdx.x; i < 4096; i += 256) {
        float4 v = p4[i];
        s  += v.x + v.y + v.z + v.w;
        ss += v.x * v.x + v.y * v.y + v.z * v.z + v.w * v.w;
    }
    __shared__ float sh[16];
    #pragma unroll
    for (int o = 16; o; o >>= 1) {
        s  += __shfl_xor_sync(0xffffffffu, s, o);
        ss += __shfl_xor_sync(0xffffffffu, ss, o);
    }
    int w = threadIdx.x >> 5;
    if ((threadIdx.x & 31) == 0) { sh[w] = s; sh[8 + w] = ss; }
    __syncthreads();
    if (threadIdx.x == 0) {
        float ts = 0.f, tss = 0.f;
        #pragma unroll
        for (int i = 0; i < 8; i++) { ts += sh[i]; tss += sh[8 + i]; }
        g_part[gi][slab][0] = ts;
        g_part[gi][slab][1] = tss;
    }
}

// ---------------- fused GN-apply + Q / (K+V) projection (bf16 mma) ------------
// grid (NS/128, BB, 2). z=0: Q from c; z=1: K AND V from x (shared input tile).
#define LDWB 136
#define LDIB 136
__global__ void __launch_bounds__(256) qkv_kernel(
    const float* __restrict__ wq, const float* __restrict__ bq,
    const float* __restrict__ wk, const float* __restrict__ bk,
    const float* __restrict__ wv, const float* __restrict__ bv,
    const float* __restrict__ g1, const float* __restrict__ b1,
    const float* __restrict__ g2, const float* __restrict__ b2,
    const float* __restrict__ x,  const float* __restrict__ cin)
{
    extern __shared__ char smraw[];
    __nv_bfloat16* WbA = (__nv_bfloat16*)smraw;               // [128][LDWB]
    __nv_bfloat16* WbB = WbA + CC * LDWB;                     // [128][LDWB] (z=1 only)
    __nv_bfloat16* In  = WbB + CC * LDWB;                     // [128][LDIB]
    float* SGA = (float*)(In + CC * LDIB);
    float* SGB = SGA + CC;

    int z = blockIdx.z;
    int b = blockIdx.y;
    int n0 = blockIdx.x * 128;
    int which = (z == 0) ? 1 : 0;
    const float* in    = which ? cin : x;
    const float* wA    = (z == 0) ? wq : wk;
    const float* gamma = which ? g2 : g1;
    const float* beta  = which ? b2 : b1;

    int tid = threadIdx.x;
    if (tid < CC) {
        int ch = tid, g = ch >> 5;
        int gi = which * 8 + b * 4 + g;
        float s = 0.f, ss = 0.f;
        #pragma unroll
        for (int k = 0; k < 8; k++) { s += g_part[gi][k][0]; ss += g_part[gi][k][1]; }
        const float invM = 1.0f / (float)(CG * NS);
        float mean = s * invM;
        float var  = ss * invM - mean * mean;
        float rinv = rsqrtf(var + 1e-6f);
        float ga = gamma[ch] * rinv;
        SGA[ch] = ga;
        SGB[ch] = beta[ch] - mean * ga;
    }
    for (int idx = tid; idx < CC * CC / 2; idx += 256) {
        int o = idx >> 6, kp = idx & 63;
        float2 w2 = *(const float2*)&wA[o * CC + kp * 2];
        ((uint32_t*)&WbA[o * LDWB])[kp] = pack_bf16(w2.x, w2.y);
    }
    if (z == 1) {
        for (int idx = tid; idx < CC * CC / 2; idx += 256) {
            int o = idx >> 6, kp = idx & 63;
            float2 w2 = *(const float2*)&wv[o * CC + kp * 2];
            ((uint32_t*)&WbB[o * LDWB])[kp] = pack_bf16(w2.x, w2.y);
        }
    }
    __syncthreads();
    for (int idx = tid; idx < CC * 32; idx += 256) {
        int c = idx >> 5, n4 = (idx & 31) * 4;
        float ga = SGA[c], be = SGB[c];
        float4 v = *(const float4*)&in[((size_t)b * CC + c) * NS + n0 + n4];
        uint32_t* dst = (uint32_t*)&In[c * LDIB + n4];
        dst[0] = pack_bf16(v.x * ga + be, v.y * ga + be);
        dst[1] = pack_bf16(v.z * ga + be, v.w * ga + be);
    }
    __syncthreads();

    int lane = tid & 31, warp = tid >> 5;
    int m0 = warp * 16;
    const int rowK = (lane & 7) + ((lane & 8) ? 8 : 0);
    const int colK = ((lane & 16) ? 8 : 0);
    int orow = m0 + (lane >> 2);
    int ncol = (lane & 3) * 2;

    for (int pass = 0; pass < (z == 1 ? 2 : 1); pass++) {
        const __nv_bfloat16* Wb = (pass == 0) ? WbA : WbB;
        const float* bias = (z == 0) ? bq : (pass == 0 ? bk : bv);
        __nv_bfloat16* out = (z == 0) ? g_qh : (pass == 0 ? g_kh : g_vh);
        float sc = (z == 0) ? QSCALE : 1.0f;

        float acc[16][4];
        #pragma unroll
        for (int nf = 0; nf < 16; nf++)
            #pragma unroll
            for (int e = 0; e < 4; e++) acc[nf][e] = 0.f;

        #pragma unroll
        for (int kb = 0; kb < 8; kb++) {
            uint32_t aw[4];
            ldsm_x4(aw, &Wb[(m0 + rowK) * LDWB + kb * 16 + colK]);
            #pragma unroll
            for (int nb = 0; nb < 8; nb++) {
                uint32_t bf[4];
                ldsm_x4t(bf, &In[(kb * 16 + rowK) * LDIB + nb * 16 + colK]);
                mma16816(acc[2 * nb],     aw, bf);
                mma16816(acc[2 * nb + 1], aw, bf + 2);
            }
        }

        float bv0 = bias[orow], bv1 = bias[orow + 8];
        size_t ob0 = ((size_t)b * CC + orow) * NS + n0;
        size_t ob1 = ob0 + (size_t)8 * NS;
        #pragma unroll
        for (int nf = 0; nf < 16; nf++) {
            int n = nf * 8 + ncol;
            *(uint32_t*)&out[ob0 + n] =
                pack_bf16((acc[nf][0] + bv0) * sc, (acc[nf][1] + bv0) * sc);
            *(uint32_t*)&out[ob1 + n] =
                pack_bf16((acc[nf][2] + bv1) * sc, (acc[nf][3] + bv1) * sc);
        }
    }
}

// ---------------- flash attention (bf16 mma, split-KV) ------------------------
// grid (NS/64, BB, SPLIT), 128 threads. Q + double-K + single-V smem (72 KB)
// -> 3 CTAs/SM.
#define LDB 72
#define SM_TILE (128 * LDB)

__global__ void __launch_bounds__(128, 3) attn_kernel()
{
    extern __shared__ __nv_bfloat16 sh[];
    __nv_bfloat16* Qs = sh;                                   // [128][LDB]
    __nv_bfloat16* Ksb[2] = { sh + SM_TILE, sh + 2 * SM_TILE };
    __nv_bfloat16* Vs = sh + 3 * SM_TILE;                     // single buffer

    int b  = blockIdx.y;
    int sp = blockIdx.z;
    int i0 = blockIdx.x * 64;
    int tid = threadIdx.x, lane = tid & 31, warp = tid >> 5;
    int t = lane & 3;
    int m0 = warp * 16;

    const __nv_bfloat16* gq = g_qh + (size_t)b * CC * NS + i0;
    const __nv_bfloat16* gk = g_kh + (size_t)b * CC * NS + sp * JSPAN;
    const __nv_bfloat16* gv = g_vh + (size_t)b * CC * NS + sp * JSPAN;

    // prologue: Q, K0, V0
    for (int idx = tid; idx < 1024; idx += 128) {
        int c = idx >> 3, j8 = (idx & 7) * 8;
        cp16(&Qs[c * LDB + j8], gq + (size_t)c * NS + j8);
        cp16(&Ksb[0][c * LDB + j8], gk + (size_t)c * NS + j8);
        cp16(&Vs[c * LDB + j8], gv + (size_t)c * NS + j8);
    }
    asm volatile("cp.async.commit_group;");
    asm volatile("cp.async.wait_group 0;");
    __syncthreads();

    const int rowA = (lane & 7) + ((lane & 16) ? 8 : 0);
    const int colA = ((lane & 8) ? 8 : 0);
    const int rowK = (lane & 7) + ((lane & 8) ? 8 : 0);
    const int colK = ((lane & 16) ? 8 : 0);

    uint32_t qa[8][4];
    #pragma unroll
    for (int kb = 0; kb < 8; kb++)
        ldsm_x4t(qa[kb], &Qs[(kb * 16 + rowA) * LDB + m0 + colA]);

    float mr0 = -1e30f, mr1 = -1e30f, lr0 = 0.f, lr1 = 0.f;
    float of[16][4];
    #pragma unroll
    for (int nt = 0; nt < 16; nt++)
        #pragma unroll
        for (int e = 0; e < 4; e++) of[nt][e] = 0.f;

    const int NT = JSPAN / 64;
    for (int jt = 0; jt < NT; jt++) {
        // K(jt) must be ready (all but newest group complete)
        asm volatile("cp.async.wait_group 1;");
        __syncthreads();

        // prefetch K(jt+1) into the other K buffer
        if (jt + 1 < NT) {
            int j0n = (jt + 1) * 64;
            __nv_bfloat16* kd = Ksb[(jt + 1) & 1];
            for (int idx = tid; idx < 1024; idx += 128) {
                int c = idx >> 3, j8 = (idx & 7) * 8;
                cp16(&kd[c * LDB + j8], gk + (size_t)c * NS + j0n + j8);
            }
        }
        asm volatile("cp.async.commit_group;");

        const __nv_bfloat16* Ks = Ksb[jt & 1];

        // ---- S = Q^T K ----
        float sf[8][4];
        #pragma unroll
        for (int nb = 0; nb < 8; nb++)
            #pragma unroll
            for (int e = 0; e < 4; e++) sf[nb][e] = 0.f;

        #pragma unroll
        for (int kb = 0; kb < 8; kb++) {
            #pragma unroll
            for (int nbp = 0; nbp < 4; nbp++) {
                uint32_t kf[4];
                ldsm_x4t(kf, &Ks[(kb * 16 + rowK) * LDB + nbp * 16 + colK]);
                mma16816(sf[2 * nbp],     qa[kb], kf);
                mma16816(sf[2 * nbp + 1], qa[kb], kf + 2);
            }
        }

        // ---- online softmax ----
        float mx0 = -1e30f, mx1 = -1e30f;
        #pragma unroll
        for (int nb = 0; nb < 8; nb++) {
            mx0 = fmaxf(mx0, fmaxf(sf[nb][0], sf[nb][1]));
            mx1 = fmaxf(mx1, fmaxf(sf[nb][2], sf[nb][3]));
        }
        mx0 = fmaxf(mx0, __shfl_xor_sync(0xffffffffu, mx0, 1));
        mx0 = fmaxf(mx0, __shfl_xor_sync(0xffffffffu, mx0, 2));
        mx1 = fmaxf(mx1, __shfl_xor_sync(0xffffffffu, mx1, 1));
        mx1 = fmaxf(mx1, __shfl_xor_sync(0xffffffffu, mx1, 2));

        float mn0 = fmaxf(mr0, mx0), mn1 = fmaxf(mr1, mx1);
        float cr0 = ex2(mr0 - mn0),  cr1 = ex2(mr1 - mn1);
        float rs0 = 0.f, rs1 = 0.f;
        #pragma unroll
        for (int nb = 0; nb < 8; nb++) {
            sf[nb][0] = ex2(sf[nb][0] - mn0);
            sf[nb][1] = ex2(sf[nb][1] - mn0);
            sf[nb][2] = ex2(sf[nb][2] - mn1);
            sf[nb][3] = ex2(sf[nb][3] - mn1);
            rs0 += sf[nb][0] + sf[nb][1];
            rs1 += sf[nb][2] + sf[nb][3];
        }
        rs0 += __shfl_xor_sync(0xffffffffu, rs0, 1);
        rs0 += __shfl_xor_sync(0xffffffffu, rs0, 2);
        rs1 += __shfl_xor_sync(0xffffffffu, rs1, 1);
        rs1 += __shfl_xor_sync(0xffffffffu, rs1, 2);
        lr0 = lr0 * cr0 + rs0;
        lr1 = lr1 * cr1 + rs1;
        mr0 = mn0; mr1 = mn1;

        #pragma unroll
        for (int nt = 0; nt < 16; nt++) {
            of[nt][0] *= cr0; of[nt][1] *= cr0;
            of[nt][2] *= cr1; of[nt][3] *= cr1;
        }

        uint32_t pa[4][4];
        #pragma unroll
        for (int kt = 0; kt < 4; kt++) {
            pa[kt][0] = pack_bf16(sf[2 * kt][0],     sf[2 * kt][1]);
            pa[kt][1] = pack_bf16(sf[2 * kt][2],     sf[2 * kt][3]);
            pa[kt][2] = pack_bf16(sf[2 * kt + 1][0], sf[2 * kt + 1][1]);
            pa[kt][3] = pack_bf16(sf[2 * kt + 1][2], sf[2 * kt + 1][3]);
        }

        // V(jt) must be ready (all but newest group = K(jt+1) complete)
        asm volatile("cp.async.wait_group 1;");
        __syncthreads();

        // ---- O += P V^T ----
        #pragma unroll
        for (int ntp = 0; ntp < 8; ntp++) {
            #pragma unroll
            for (int kt = 0; kt < 4; kt++) {
                uint32_t vf[4];
                ldsm_x4(vf, &Vs[(ntp * 16 + rowA) * LDB + kt * 16 + colA]);
                mma16816(of[2 * ntp],     pa[kt], vf);
                mma16816(of[2 * ntp + 1], pa[kt], vf + 2);
            }
        }
        __syncthreads();   // all warps done reading Vs

        // prefetch V(jt+1) into (now free) Vs
        if (jt + 1 < NT) {
            int j0n = (jt + 1) * 64;
            for (int idx = tid; idx < 1024; idx += 128) {
                int c = idx >> 3, j8 = (idx & 7) * 8;
                cp16(&Vs[c * LDB + j8], gv + (size_t)c * NS + j0n + j8);
            }
        }
        asm volatile("cp.async.commit_group;");
    }
    asm volatile("cp.async.wait_group 0;");

    // epilogue: per-split-normalized bf16 partials, [n][c] layout
    float inv0 = 1.0f / lr0, inv1 = 1.0f / lr1;
    int ig = i0 + m0 + (lane >> 2);
    __nv_bfloat16* po = g_pob + ((size_t)(sp * BB + b)) * NS * CC;
    #pragma unroll
    for (int nt = 0; nt < 16; nt++) {
        int c = 8 * nt + 2 * t;
        *(uint32_t*)&po[(size_t)ig * CC + c] =
            pack_bf16(of[nt][0] * inv0, of[nt][1] * inv0);
        *(uint32_t*)&po[(size_t)(ig + 8) * CC + c] =
            pack_bf16(of[nt][2] * inv1, of[nt][3] * inv1);
    }
    if (t == 0) {
        size_t mb = (size_t)(sp * BB + b) * NS;
        g_pm[mb + ig]     = mr0;
        g_pm[mb + ig + 8] = mr1;
        g_pl[mb + ig]     = lr0;
        g_pl[mb + ig + 8] = lr1;
    }
}

// ---------------- fused split-combine + output projection (bf16 mma) ----------
// grid (NS/64, BB), 256 threads. Combined input kept [n][c] -> non-trans ldsm.
#define LDC 136
__global__ void __launch_bounds__(256) proj_out_kernel(
    const float* __restrict__ w, const float* __restrict__ bias,
    const float* __restrict__ xres, float* __restrict__ out)
{
    extern __shared__ char smraw[];
    __nv_bfloat16* Wb = (__nv_bfloat16*)smraw;         // [128][LDWB]
    __nv_bfloat16* In = Wb + CC * LDWB;                // [64 n][LDC c]
    float* A0 = (float*)(In + 64 * LDC);               // [64]
    float* A1 = A0 + 64;

    int b  = blockIdx.y;
    int n0 = blockIdx.x * 64;
    int tid = threadIdx.x;

    if (tid < 64) {
        int i = n0 + tid;
        float m0v = g_pm[(size_t)b * NS + i];
        float m1v = g_pm[(size_t)(BB + b) * NS + i];
        float l0v = g_pl[(size_t)b * NS + i];
        float l1v = g_pl[(size_t)(BB + b) * NS + i];
        float mm = fmaxf(m0v, m1v);
        float e0 = l0v * ex2(m0v - mm), e1 = l1v * ex2(m1v - mm);
        float inv = 1.0f / (e0 + e1);
        A0[tid] = e0 * inv;
        A1[tid] = e1 * inv;
    }
    for (int idx = tid; idx < CC * CC / 2; idx += 256) {
        int o = idx >> 6, kp = idx & 63;
        float2 w2 = *(const float2*)&w[o * CC + kp * 2];
        ((uint32_t*)&Wb[o * LDWB])[kp] = pack_bf16(w2.x, w2.y);
    }
    __syncthreads();

    // combine bf16 partials: In[n][c] = A0[n]*po0[n][c] + A1[n]*po1[n][c]
    const __nv_bfloat16* po0 = g_pob + (size_t)b * NS * CC;
    const __nv_bfloat16* po1 = g_pob + (size_t)(BB + b) * NS * CC;
    for (int idx = tid; idx < 64 * 64; idx += 256) {
        int n = idx >> 6, cp = (idx & 63);
        size_t gaddr = (size_t)(n0 + n) * CC + cp * 2;
        uint32_t u0 = *(const uint32_t*)&po0[gaddr];
        uint32_t u1 = *(const uint32_t*)&po1[gaddr];
        __nv_bfloat162 h0 = *(__nv_bfloat162*)&u0;
        __nv_bfloat162 h1 = *(__nv_bfloat162*)&u1;
        float a0 = A0[n], a1 = A1[n];
        float rx = a0 * __bfloat162float(h0.x) + a1 * __bfloat162float(h1.x);
        float ry = a0 * __bfloat162float(h0.y) + a1 * __bfloat162float(h1.y);
        ((uint32_t*)&In[n * LDC])[cp] = pack_bf16(rx, ry);
    }
    __syncthreads();

    int lane = tid & 31, warp = tid >> 5;
    int m0 = warp * 16;
    const int rowA = (lane & 7) + ((lane & 16) ? 8 : 0);
    const int colA = ((lane & 8) ? 8 : 0);
    const int rowK = (lane & 7) + ((lane & 8) ? 8 : 0);
    const int colK = ((lane & 16) ? 8 : 0);

    float acc[8][4];
    #pragma unroll
    for (int nf = 0; nf < 8; nf++)
        #pragma unroll
        for (int e = 0; e < 4; e++) acc[nf][e] = 0.f;

    #pragma unroll
    for (int kb = 0; kb < 8; kb++) {
        uint32_t aw[4];
        ldsm_x4(aw, &Wb[(m0 + rowK) * LDWB + kb * 16 + colK]);
        #pragma unroll
        for (int nb = 0; nb < 4; nb++) {
            uint32_t vf[4];
            ldsm_x4(vf, &In[(nb * 16 + rowA) * LDC + kb * 16 + colA]);
            mma16816(acc[2 * nb],     aw, vf);
            mma16816(acc[2 * nb + 1], aw, vf + 2);
        }
    }

    int orow = m0 + (lane >> 2);
    int ncol = (lane & 3) * 2;
    float bv0 = bias[orow], bv1 = bias[orow + 8];
    size_t ob0 = ((size_t)b * CC + orow) * NS + n0;
    size_t ob1 = ob0 + (size_t)8 * NS;
    #pragma unroll
    for (int nf = 0; nf < 8; nf++) {
        int n = nf * 8 + ncol;
        float2 x0 = *(const float2*)&xres[ob0 + n];
        float2 x1 = *(const float2*)&xres[ob1 + n];
        float2 r0 = { acc[nf][0] + bv0 + x0.x, acc[nf][1] + bv0 + x0.y };
        float2 r1 = { acc[nf][2] + bv1 + x1.x, acc[nf][3] + bv1 + x1.y };
        *(float2*)&out[ob0 + n] = r0;
        *(float2*)&out[ob1 + n] = r1;
    }
}

// ---------------- launcher ---------------------------------------------------
extern "C" void kernel_launch(void* const* d_in, const int* in_sizes, int n_in,
                              void* d_out, int out_size)
{
    const float* x  = (const float*)d_in[0];
    const float* c  = (const float*)d_in[1];
    const float* g1 = (const float*)d_in[2];
    const float* b1 = (const float*)d_in[3];
    const float* g2 = (const float*)d_in[4];
    const float* b2 = (const float*)d_in[5];
    const float* wq = (const float*)d_in[6];
    const float* bq = (const float*)d_in[7];
    const float* wk = (const float*)d_in[8];
    const float* bk = (const float*)d_in[9];
    const float* wv = (const float*)d_in[10];
    const float* bv = (const float*)d_in[11];
    const float* wp = (const float*)d_in[12];
    const float* bp = (const float*)d_in[13];
    float* out = (float*)d_out;

    const int QKV_SMEM  = (2 * CC * LDWB + CC * LDIB) * 2 + 2 * CC * 4;  // 105472
    const int PROJ_SMEM = (CC * LDWB + 64 * LDC) * 2 + 2 * 64 * 4;       // 52736
    const int ATTN_SMEM = 4 * SM_TILE * 2;                               // 73728
    cudaFuncSetAttribute(qkv_kernel,      cudaFuncAttributeMaxDynamicSharedMemorySize, QKV_SMEM);
    cudaFuncSetAttribute(proj_out_kernel, cudaFuncAttributeMaxDynamicSharedMemorySize, PROJ_SMEM);
    cudaFuncSetAttribute(attn_kernel,     cudaFuncAttributeMaxDynamicSharedMemorySize, ATTN_SMEM);

    gn_stats_kernel<<<dim3(8, 16), 256>>>(x, c);

    dim3 gq(NS / 128, BB, 2);
    qkv_kernel<<<gq, 256, QKV_SMEM>>>(wq, bq, wk, bk, wv, bv,
                                      g1, b1, g2, b2, x, c);

    dim3 ga(NS / 64, BB, SPLIT);
    attn_kernel<<<ga, 128, ATTN_SMEM>>>();

    dim3 gp(NS / 64, BB);
    proj_out_kernel<<<gp, 256, PROJ_SMEM>>>(wp, bp, x, out);
}

// round 6
// speedup vs baseline: 11.5029x; 1.0960x over previous
#include <cuda_runtime.h>
#include <cuda_bf16.h>
#include <math.h>
#include <stdint.h>

// Problem constants
#define BB 2
#define CC 128
#define GG 4
#define CG 32
#define NS 4096
#define SPLIT 2
#define JSPAN (NS / SPLIT)
// 128^-0.5 * log2(e): fold into Q so softmax works in exp2 domain
#define QSCALE 0.12751744154339495f

// ---------------- scratch (device globals) ----------------------------------
__device__ __nv_bfloat16 g_qh[BB * CC * NS];    // Q * QSCALE, bf16, [b][c][n]
__device__ __nv_bfloat16 g_kh[BB * CC * NS];
__device__ __nv_bfloat16 g_vh[BB * CC * NS];
__device__ __nv_bfloat16 g_pob[SPLIT * BB * NS * CC]; // per-split normalized O, [sp][b][n][c]
__device__ float g_pm[SPLIT * BB * NS];         // partial row max (log2 domain)
__device__ float g_pl[SPLIT * BB * NS];         // partial row sum
__device__ float g_part[16][8][2];              // GN partials [group][slab][sum,ssq]
__device__ __nv_bfloat16 g_wb[4 * CC * CC];     // bf16 weights: q,k,v,p  [o][c]

// ---------------- asm helpers -------------------------------------------------
__device__ __forceinline__ float ex2(float x) {
    float r; asm("ex2.approx.ftz.f32 %0, %1;" : "=f"(r) : "f"(x)); return r;
}
__device__ __forceinline__ uint32_t pack_bf16(float lo, float hi) {
    uint32_t d;
    asm("cvt.rn.bf16x2.f32 %0, %1, %2;" : "=r"(d) : "f"(hi), "f"(lo));
    return d;
}
__device__ __forceinline__ void cp16(void* dst_smem, const void* src) {
    uint32_t d = (uint32_t)__cvta_generic_to_shared(dst_smem);
    asm volatile("cp.async.cg.shared.global [%0], [%1], 16;\n" :: "r"(d), "l"(src));
}
__device__ __forceinline__ void ldsm_x4(uint32_t* r, const void* p) {
    uint32_t a = (uint32_t)__cvta_generic_to_shared(p);
    asm volatile("ldmatrix.sync.aligned.m8n8.x4.shared.b16 {%0,%1,%2,%3}, [%4];"
        : "=r"(r[0]), "=r"(r[1]), "=r"(r[2]), "=r"(r[3]) : "r"(a));
}
__device__ __forceinline__ void ldsm_x4t(uint32_t* r, const void* p) {
    uint32_t a = (uint32_t)__cvta_generic_to_shared(p);
    asm volatile("ldmatrix.sync.aligned.m8n8.x4.trans.shared.b16 {%0,%1,%2,%3}, [%4];"
        : "=r"(r[0]), "=r"(r[1]), "=r"(r[2]), "=r"(r[3]) : "r"(a));
}
__device__ __forceinline__ void mma16816(float* d, const uint32_t* a, const uint32_t* b) {
    asm volatile(
        "mma.sync.aligned.m16n8k16.row.col.f32.bf16.bf16.f32 "
        "{%0,%1,%2,%3},{%4,%5,%6,%7},{%8,%9},{%0,%1,%2,%3};"
        : "+f"(d[0]), "+f"(d[1]), "+f"(d[2]), "+f"(d[3])
        : "r"(a[0]), "r"(a[1]), "r"(a[2]), "r"(a[3]), "r"(b[0]), "r"(b[1]));
}

// ---------------- prep: GN partial stats + weight bf16 conversion --------------
// grid 192: blocks 0..127 = stats (gi = blk>>3, slab = blk&7); 128..191 = W conv.
__global__ void __launch_bounds__(256) prep_kernel(
    const float* __restrict__ x, const float* __restrict__ c,
    const float* __restrict__ wq, const float* __restrict__ wk,
    const float* __restrict__ wv, const float* __restrict__ wp)
{
    int blk = blockIdx.x;
    if (blk >= 128) {
        // weight conversion: 4*16384 floats -> 32768 bf16x2 pairs
        int blk2 = blk - 128;                 // 0..63
        const float* ws[4] = { wq, wk, wv, wp };
        #pragma unroll
        for (int it = 0; it < 2; it++) {
            int p = blk2 * 512 + it * 256 + (int)threadIdx.x;   // pair index
            int w_id = p >> 13, off = p & 8191;
            float2 w2 = *(const float2*)&ws[w_id][off * 2];
            ((uint32_t*)g_wb)[p] = pack_bf16(w2.x, w2.y);
        }
        return;
    }
    int slab = blk & 7;
    int gi   = blk >> 3;
    int which = gi >> 3, b = (gi >> 2) & 1, g = gi & 3;
    const float* in = which ? c : x;
    const float4* p4 = (const float4*)(in + ((size_t)(b * CC + g * CG)) * NS) +
                       (size_t)slab * 4096;

    float s = 0.f, ss = 0.f;
    #pragma unroll 4
    for (int i = threadIdx.x; i < 4096; i += 256) {
        float4 v = p4[i];
        s  += v.x + v.y + v.z + v.w;
        ss += v.x * v.x + v.y * v.y + v.z * v.z + v.w * v.w;
    }
    __shared__ float sh[16];
    #pragma unroll
    for (int o = 16; o; o >>= 1) {
        s  += __shfl_xor_sync(0xffffffffu, s, o);
        ss += __shfl_xor_sync(0xffffffffu, ss, o);
    }
    int w = threadIdx.x >> 5;
    if ((threadIdx.x & 31) == 0) { sh[w] = s; sh[8 + w] = ss; }
    __syncthreads();
    if (threadIdx.x == 0) {
        float ts = 0.f, tss = 0.f;
        #pragma unroll
        for (int i = 0; i < 8; i++) { ts += sh[i]; tss += sh[8 + i]; }
        g_part[gi][slab][0] = ts;
        g_part[gi][slab][1] = tss;
    }
}

// ---------------- fused GN-apply + Q / (K+V) projection (bf16 mma) ------------
// grid (NS/64, BB, 2). z=0: Q from c; z=1: K AND V from x (shared input tile).
// 256 threads = 8 warps, warp owns 16 out rows x 64 tokens.
#define LDWB 136   // bf16 pitch for W [o][c] (272B)
#define LDRF 68    // fp32 pitch for raw input [c][n] (272B)
#define LDIB 72    // bf16 pitch for In [c][n] (144B)
__global__ void __launch_bounds__(256) qkv_kernel(
    const float* __restrict__ bq, const float* __restrict__ bk,
    const float* __restrict__ bv,
    const float* __restrict__ g1, const float* __restrict__ b1,
    const float* __restrict__ g2, const float* __restrict__ b2,
    const float* __restrict__ x,  const float* __restrict__ cin)
{
    extern __shared__ char smraw[];
    __nv_bfloat16* WbA = (__nv_bfloat16*)smraw;               // [128][LDWB]
    __nv_bfloat16* WbB = WbA + CC * LDWB;                     // [128][LDWB] (z=1)
    float*         Raw = (float*)(WbB + CC * LDWB);           // [128][LDRF]
    __nv_bfloat16* In  = (__nv_bfloat16*)(Raw + CC * LDRF);   // [128][LDIB]
    float* SGA = (float*)(In + CC * LDIB);
    float* SGB = SGA + CC;

    int z = blockIdx.z;
    int b = blockIdx.y;
    int n0 = blockIdx.x * 64;
    int which = (z == 0) ? 1 : 0;
    const float* in    = which ? cin : x;
    const float* gamma = which ? g2 : g1;
    const float* beta  = which ? b2 : b1;
    const __nv_bfloat16* wA = g_wb + (z == 0 ? 0 : 1) * CC * CC;
    const __nv_bfloat16* wB = g_wb + 2 * CC * CC;

    int tid = threadIdx.x;

    // async loads: weights (bf16) + raw input tile (fp32), all one group
    for (int idx = tid; idx < 2048; idx += 256) {
        int o = idx >> 4, ch = idx & 15;
        cp16(&WbA[o * LDWB + ch * 8], wA + o * CC + ch * 8);
    }
    if (z == 1) {
        for (int idx = tid; idx < 2048; idx += 256) {
            int o = idx >> 4, ch = idx & 15;
            cp16(&WbB[o * LDWB + ch * 8], wB + o * CC + ch * 8);
        }
    }
    for (int idx = tid; idx < 2048; idx += 256) {
        int c = idx >> 4, ch = idx & 15;
        cp16(&Raw[c * LDRF + ch * 4], &in[((size_t)b * CC + c) * NS + n0 + ch * 4]);
    }
    asm volatile("cp.async.commit_group;");

    // overlap: GN affine coefficients
    if (tid < CC) {
        int chn = tid, g = chn >> 5;
        int gi = which * 8 + b * 4 + g;
        float s = 0.f, ss = 0.f;
        #pragma unroll
        for (int k = 0; k < 8; k++) { s += g_part[gi][k][0]; ss += g_part[gi][k][1]; }
        const float invM = 1.0f / (float)(CG * NS);
        float mean = s * invM;
        float var  = ss * invM - mean * mean;
        float rinv = rsqrtf(var + 1e-6f);
        float ga = gamma[chn] * rinv;
        SGA[chn] = ga;
        SGB[chn] = beta[chn] - mean * ga;
    }
    asm volatile("cp.async.wait_group 0;");
    __syncthreads();

    // normalize fp32 -> bf16
    for (int idx = tid; idx < 2048; idx += 256) {
        int c = idx >> 4, q = idx & 15;
        float ga = SGA[c], be = SGB[c];
        float4 v = *(const float4*)&Raw[c * LDRF + q * 4];
        uint32_t* dst = (uint32_t*)&In[c * LDIB + q * 4];
        dst[0] = pack_bf16(v.x * ga + be, v.y * ga + be);
        dst[1] = pack_bf16(v.z * ga + be, v.w * ga + be);
    }
    __syncthreads();

    int lane = tid & 31, warp = tid >> 5;
    int m0 = warp * 16;
    const int rowK = (lane & 7) + ((lane & 8) ? 8 : 0);
    const int colK = ((lane & 16) ? 8 : 0);
    int orow = m0 + (lane >> 2);
    int ncol = (lane & 3) * 2;

    for (int pass = 0; pass < (z == 1 ? 2 : 1); pass++) {
        const __nv_bfloat16* Wb = (pass == 0) ? WbA : WbB;
        const float* bias = (z == 0) ? bq : (pass == 0 ? bk : bv);
        __nv_bfloat16* out = (z == 0) ? g_qh : (pass == 0 ? g_kh : g_vh);
        float sc = (z == 0) ? QSCALE : 1.0f;

        float acc[8][4];
        #pragma unroll
        for (int nf = 0; nf < 8; nf++)
            #pragma unroll
            for (int e = 0; e < 4; e++) acc[nf][e] = 0.f;

        #pragma unroll
        for (int kb = 0; kb < 8; kb++) {
            uint32_t aw[4];
            ldsm_x4(aw, &Wb[(m0 + rowK) * LDWB + kb * 16 + colK]);
            #pragma unroll
            for (int nb = 0; nb < 4; nb++) {
                uint32_t bf[4];
                ldsm_x4t(bf, &In[(kb * 16 + rowK) * LDIB + nb * 16 + colK]);
                mma16816(acc[2 * nb],     aw, bf);
                mma16816(acc[2 * nb + 1], aw, bf + 2);
            }
        }

        float bv0 = bias[orow], bv1 = bias[orow + 8];
        size_t ob0 = ((size_t)b * CC + orow) * NS + n0;
        size_t ob1 = ob0 + (size_t)8 * NS;
        #pragma unroll
        for (int nf = 0; nf < 8; nf++) {
            int n = nf * 8 + ncol;
            *(uint32_t*)&out[ob0 + n] =
                pack_bf16((acc[nf][0] + bv0) * sc, (acc[nf][1] + bv0) * sc);
            *(uint32_t*)&out[ob1 + n] =
                pack_bf16((acc[nf][2] + bv1) * sc, (acc[nf][3] + bv1) * sc);
        }
    }
}

// ---------------- flash attention (bf16 mma, split-KV) ------------------------
#define LDB 72
#define SM_TILE (128 * LDB)

__global__ void __launch_bounds__(128, 3) attn_kernel()
{
    extern __shared__ __nv_bfloat16 sh[];
    __nv_bfloat16* Qs = sh;
    __nv_bfloat16* Ksb[2] = { sh + SM_TILE, sh + 2 * SM_TILE };
    __nv_bfloat16* Vs = sh + 3 * SM_TILE;

    int b  = blockIdx.y;
    int sp = blockIdx.z;
    int i0 = blockIdx.x * 64;
    int tid = threadIdx.x, lane = tid & 31, warp = tid >> 5;
    int t = lane & 3;
    int m0 = warp * 16;

    const __nv_bfloat16* gq = g_qh + (size_t)b * CC * NS + i0;
    const __nv_bfloat16* gk = g_kh + (size_t)b * CC * NS + sp * JSPAN;
    const __nv_bfloat16* gv = g_vh + (size_t)b * CC * NS + sp * JSPAN;

    for (int idx = tid; idx < 1024; idx += 128) {
        int c = idx >> 3, j8 = (idx & 7) * 8;
        cp16(&Qs[c * LDB + j8], gq + (size_t)c * NS + j8);
        cp16(&Ksb[0][c * LDB + j8], gk + (size_t)c * NS + j8);
        cp16(&Vs[c * LDB + j8], gv + (size_t)c * NS + j8);
    }
    asm volatile("cp.async.commit_group;");
    asm volatile("cp.async.wait_group 0;");
    __syncthreads();

    const int rowA = (lane & 7) + ((lane & 16) ? 8 : 0);
    const int colA = ((lane & 8) ? 8 : 0);
    const int rowK = (lane & 7) + ((lane & 8) ? 8 : 0);
    const int colK = ((lane & 16) ? 8 : 0);

    uint32_t qa[8][4];
    #pragma unroll
    for (int kb = 0; kb < 8; kb++)
        ldsm_x4t(qa[kb], &Qs[(kb * 16 + rowA) * LDB + m0 + colA]);

    float mr0 = -1e30f, mr1 = -1e30f, lr0 = 0.f, lr1 = 0.f;
    float of[16][4];
    #pragma unroll
    for (int nt = 0; nt < 16; nt++)
        #pragma unroll
        for (int e = 0; e < 4; e++) of[nt][e] = 0.f;

    const int NT = JSPAN / 64;
    for (int jt = 0; jt < NT; jt++) {
        asm volatile("cp.async.wait_group 1;");
        __syncthreads();

        if (jt + 1 < NT) {
            int j0n = (jt + 1) * 64;
            __nv_bfloat16* kd = Ksb[(jt + 1) & 1];
            for (int idx = tid; idx < 1024; idx += 128) {
                int c = idx >> 3, j8 = (idx & 7) * 8;
                cp16(&kd[c * LDB + j8], gk + (size_t)c * NS + j0n + j8);
            }
        }
        asm volatile("cp.async.commit_group;");

        const __nv_bfloat16* Ks = Ksb[jt & 1];

        float sf[8][4];
        #pragma unroll
        for (int nb = 0; nb < 8; nb++)
            #pragma unroll
            for (int e = 0; e < 4; e++) sf[nb][e] = 0.f;

        #pragma unroll
        for (int kb = 0; kb < 8; kb++) {
            #pragma unroll
            for (int nbp = 0; nbp < 4; nbp++) {
                uint32_t kf[4];
                ldsm_x4t(kf, &Ks[(kb * 16 + rowK) * LDB + nbp * 16 + colK]);
                mma16816(sf[2 * nbp],     qa[kb], kf);
                mma16816(sf[2 * nbp + 1], qa[kb], kf + 2);
            }
        }

        float mx0 = -1e30f, mx1 = -1e30f;
        #pragma unroll
        for (int nb = 0; nb < 8; nb++) {
            mx0 = fmaxf(mx0, fmaxf(sf[nb][0], sf[nb][1]));
            mx1 = fmaxf(mx1, fmaxf(sf[nb][2], sf[nb][3]));
        }
        mx0 = fmaxf(mx0, __shfl_xor_sync(0xffffffffu, mx0, 1));
        mx0 = fmaxf(mx0, __shfl_xor_sync(0xffffffffu, mx0, 2));
        mx1 = fmaxf(mx1, __shfl_xor_sync(0xffffffffu, mx1, 1));
        mx1 = fmaxf(mx1, __shfl_xor_sync(0xffffffffu, mx1, 2));

        float mn0 = fmaxf(mr0, mx0), mn1 = fmaxf(mr1, mx1);
        float cr0 = ex2(mr0 - mn0),  cr1 = ex2(mr1 - mn1);
        float rs0 = 0.f, rs1 = 0.f;
        #pragma unroll
        for (int nb = 0; nb < 8; nb++) {
            sf[nb][0] = ex2(sf[nb][0] - mn0);
            sf[nb][1] = ex2(sf[nb][1] - mn0);
            sf[nb][2] = ex2(sf[nb][2] - mn1);
            sf[nb][3] = ex2(sf[nb][3] - mn1);
            rs0 += sf[nb][0] + sf[nb][1];
            rs1 += sf[nb][2] + sf[nb][3];
        }
        rs0 += __shfl_xor_sync(0xffffffffu, rs0, 1);
        rs0 += __shfl_xor_sync(0xffffffffu, rs0, 2);
        rs1 += __shfl_xor_sync(0xffffffffu, rs1, 1);
        rs1 += __shfl_xor_sync(0xffffffffu, rs1, 2);
        lr0 = lr0 * cr0 + rs0;
        lr1 = lr1 * cr1 + rs1;
        mr0 = mn0; mr1 = mn1;

        #pragma unroll
        for (int nt = 0; nt < 16; nt++) {
            of[nt][0] *= cr0; of[nt][1] *= cr0;
            of[nt][2] *= cr1; of[nt][3] *= cr1;
        }

        uint32_t pa[4][4];
        #pragma unroll
        for (int kt = 0; kt < 4; kt++) {
            pa[kt][0] = pack_bf16(sf[2 * kt][0],     sf[2 * kt][1]);
            pa[kt][1] = pack_bf16(sf[2 * kt][2],     sf[2 * kt][3]);
            pa[kt][2] = pack_bf16(sf[2 * kt + 1][0], sf[2 * kt + 1][1]);
            pa[kt][3] = pack_bf16(sf[2 * kt + 1][2], sf[2 * kt + 1][3]);
        }

        asm volatile("cp.async.wait_group 1;");
        __syncthreads();

        #pragma unroll
        for (int ntp = 0; ntp < 8; ntp++) {
            #pragma unroll
            for (int kt = 0; kt < 4; kt++) {
                uint32_t vf[4];
                ldsm_x4(vf, &Vs[(ntp * 16 + rowA) * LDB + kt * 16 + colA]);
                mma16816(of[2 * ntp],     pa[kt], vf);
                mma16816(of[2 * ntp + 1], pa[kt], vf + 2);
            }
        }
        __syncthreads();

        if (jt + 1 < NT) {
            int j0n = (jt + 1) * 64;
            for (int idx = tid; idx < 1024; idx += 128) {
                int c = idx >> 3, j8 = (idx & 7) * 8;
                cp16(&Vs[c * LDB + j8], gv + (size_t)c * NS + j0n + j8);
            }
        }
        asm volatile("cp.async.commit_group;");
    }
    asm volatile("cp.async.wait_group 0;");

    float inv0 = 1.0f / lr0, inv1 = 1.0f / lr1;
    int ig = i0 + m0 + (lane >> 2);
    __nv_bfloat16* po = g_pob + ((size_t)(sp * BB + b)) * NS * CC;
    #pragma unroll
    for (int nt = 0; nt < 16; nt++) {
        int c = 8 * nt + 2 * t;
        *(uint32_t*)&po[(size_t)ig * CC + c] =
            pack_bf16(of[nt][0] * inv0, of[nt][1] * inv0);
        *(uint32_t*)&po[(size_t)(ig + 8) * CC + c] =
            pack_bf16(of[nt][2] * inv1, of[nt][3] * inv1);
    }
    if (t == 0) {
        size_t mb = (size_t)(sp * BB + b) * NS;
        g_pm[mb + ig]     = mr0;
        g_pm[mb + ig + 8] = mr1;
        g_pl[mb + ig]     = lr0;
        g_pl[mb + ig + 8] = lr1;
    }
}

// ---------------- fused split-combine + output projection (bf16 mma) ----------
// grid (NS/64, BB, 2). z = M-half (64 out rows). 128 threads = 4 warps.
#define LDC 136
__global__ void __launch_bounds__(128) proj_out_kernel(
    const float* __restrict__ bias,
    const float* __restrict__ xres, float* __restrict__ out)
{
    extern __shared__ char smraw[];
    __nv_bfloat16* Wb = (__nv_bfloat16*)smraw;        // [64][LDC]
    __nv_bfloat16* P0 = Wb + 64 * LDC;                // [64 n][LDC c]
    __nv_bfloat16* P1 = P0 + 64 * LDC;                // [64 n][LDC c]
    __nv_bfloat16* In = P1 + 64 * LDC;                // [64 n][LDC c]
    float* A0 = (float*)(In + 64 * LDC);              // [64]
    float* A1 = A0 + 64;

    int b  = blockIdx.y;
    int mh = blockIdx.z;
    int n0 = blockIdx.x * 64;
    int tid = threadIdx.x;

    const __nv_bfloat16* wsrc = g_wb + 3 * CC * CC + (size_t)(mh * 64) * CC;
    const __nv_bfloat16* po0 = g_pob + (size_t)b * NS * CC + (size_t)n0 * CC;
    const __nv_bfloat16* po1 = g_pob + (size_t)(BB + b) * NS * CC + (size_t)n0 * CC;

    // async: W half + both partial tiles
    for (int idx = tid; idx < 1024; idx += 128) {
        int r = idx >> 4, ch = (idx & 15) * 8;
        cp16(&Wb[r * LDC + ch], wsrc + r * CC + ch);
        cp16(&P0[r * LDC + ch], po0 + r * CC + ch);
        cp16(&P1[r * LDC + ch], po1 + r * CC + ch);
    }
    asm volatile("cp.async.commit_group;");

    // overlap: combine coefficients
    if (tid < 64) {
        int i = n0 + tid;
        float m0v = g_pm[(size_t)b * NS + i];
        float m1v = g_pm[(size_t)(BB + b) * NS + i];
        float l0v = g_pl[(size_t)b * NS + i];
        float l1v = g_pl[(size_t)(BB + b) * NS + i];
        float mm = fmaxf(m0v, m1v);
        float e0 = l0v * ex2(m0v - mm), e1 = l1v * ex2(m1v - mm);
        float inv = 1.0f / (e0 + e1);
        A0[tid] = e0 * inv;
        A1[tid] = e1 * inv;
    }
    asm volatile("cp.async.wait_group 0;");
    __syncthreads();

    // combine: In[n][c] = A0[n]*P0[n][c] + A1[n]*P1[n][c]
    for (int idx = tid; idx < 64 * 64; idx += 128) {
        int n = idx >> 6, cp = idx & 63;
        uint32_t u0 = ((const uint32_t*)&P0[n * LDC])[cp];
        uint32_t u1 = ((const uint32_t*)&P1[n * LDC])[cp];
        __nv_bfloat162 h0 = *(__nv_bfloat162*)&u0;
        __nv_bfloat162 h1 = *(__nv_bfloat162*)&u1;
        float a0 = A0[n], a1 = A1[n];
        float rx = a0 * __bfloat162float(h0.x) + a1 * __bfloat162float(h1.x);
        float ry = a0 * __bfloat162float(h0.y) + a1 * __bfloat162float(h1.y);
        ((uint32_t*)&In[n * LDC])[cp] = pack_bf16(rx, ry);
    }
    __syncthreads();

    int lane = tid & 31, warp = tid >> 5;
    int m0 = warp * 16;
    const int rowA = (lane & 7) + ((lane & 16) ? 8 : 0);
    const int colA = ((lane & 8) ? 8 : 0);
    const int rowK = (lane & 7) + ((lane & 8) ? 8 : 0);
    const int colK = ((lane & 16) ? 8 : 0);

    float acc[8][4];
    #pragma unroll
    for (int nf = 0; nf < 8; nf++)
        #pragma unroll
        for (int e = 0; e < 4; e++) acc[nf][e] = 0.f;

    #pragma unroll
    for (int kb = 0; kb < 8; kb++) {
        uint32_t aw[4];
        ldsm_x4(aw, &Wb[(m0 + rowK) * LDC + kb * 16 + colK]);
        #pragma unroll
        for (int nb = 0; nb < 4; nb++) {
            uint32_t vf[4];
            ldsm_x4(vf, &In[(nb * 16 + rowA) * LDC + kb * 16 + colA]);
            mma16816(acc[2 * nb],     aw, vf);
            mma16816(acc[2 * nb + 1], aw, vf + 2);
        }
    }

    int orow = mh * 64 + m0 + (lane >> 2);
    int ncol = (lane & 3) * 2;
    float bv0 = bias[orow], bv1 = bias[orow + 8];
    size_t ob0 = ((size_t)b * CC + orow) * NS + n0;
    size_t ob1 = ob0 + (size_t)8 * NS;
    #pragma unroll
    for (int nf = 0; nf < 8; nf++) {
        int n = nf * 8 + ncol;
        float2 x0 = *(const float2*)&xres[ob0 + n];
        float2 x1 = *(const float2*)&xres[ob1 + n];
        float2 r0 = { acc[nf][0] + bv0 + x0.x, acc[nf][1] + bv0 + x0.y };
        float2 r1 = { acc[nf][2] + bv1 + x1.x, acc[nf][3] + bv1 + x1.y };
        *(float2*)&out[ob0 + n] = r0;
        *(float2*)&out[ob1 + n] = r1;
    }
}

// ---------------- launcher ---------------------------------------------------
extern "C" void kernel_launch(void* const* d_in, const int* in_sizes, int n_in,
                              void* d_out, int out_size)
{
    const float* x  = (const float*)d_in[0];
    const float* c  = (const float*)d_in[1];
    const float* g1 = (const float*)d_in[2];
    const float* b1 = (const float*)d_in[3];
    const float* g2 = (const float*)d_in[4];
    const float* b2 = (const float*)d_in[5];
    const float* wq = (const float*)d_in[6];
    const float* bq = (const float*)d_in[7];
    const float* wk = (const float*)d_in[8];
    const float* bk = (const float*)d_in[9];
    const float* wv = (const float*)d_in[10];
    const float* bv = (const float*)d_in[11];
    const float* wp = (const float*)d_in[12];
    const float* bp = (const float*)d_in[13];
    float* out = (float*)d_out;

    const int QKV_SMEM  = (2 * CC * LDWB + CC * LDIB) * 2 + CC * LDRF * 4 + 2 * CC * 4;
    const int PROJ_SMEM = 4 * 64 * LDC * 2 + 2 * 64 * 4;
    const int ATTN_SMEM = 4 * SM_TILE * 2;
    cudaFuncSetAttribute(qkv_kernel,      cudaFuncAttributeMaxDynamicSharedMemorySize, QKV_SMEM);
    cudaFuncSetAttribute(proj_out_kernel, cudaFuncAttributeMaxDynamicSharedMemorySize, PROJ_SMEM);
    cudaFuncSetAttribute(attn_kernel,     cudaFuncAttributeMaxDynamicSharedMemorySize, ATTN_SMEM);

    prep_kernel<<<192, 256>>>(x, c, wq, wk, wv, wp);

    dim3 gq(NS / 64, BB, 2);
    qkv_kernel<<<gq, 256, QKV_SMEM>>>(bq, bk, bv, g1, b1, g2, b2, x, c);

    dim3 ga(NS / 64, BB, SPLIT);
    attn_kernel<<<ga, 128, ATTN_SMEM>>>();

    dim3 gp(NS / 64, BB, 2);
    proj_out_kernel<<<gp, 128, PROJ_SMEM>>>(bp, x, out);
}